// round 13
// baseline (speedup 1.0000x reference)
#include <cuda_runtime.h>

#define NS   512
#define NS2  (NS * NS)
#define TN   20000
#define ND   2000
#define DTC  30.0f
#define RAD  8          // fill radix (anchors every 8 rows)
#define NANCH 2500      // TN / RAD
#define SKROWS 1280     // split-K partial rows for anchor BK (max cnt = 1250)

// ---------------- static scratch (no allocations allowed) ----------------
__device__ float d_Lt[NS2];               // (dt*A)^T
__device__ float d_G1[NS2];               // Lt^2
__device__ float d_G2[NS2];               // H = Lt/6 + Lt^2/24
// T slots: 0 = Horner base ; 1..8 = (M^q)^T ; 9=T16,10=T32,11=T64,12=T128
__device__ float d_T[13][NS2];
__device__ float d_vec[8 * NS];
__device__ float d_vw[RAD * 5 * NS];      // vw[j] = M^j [w1..w4, v]
__device__ float d_cv[RAD * NS];          // cv[p-1] = sum_{j<p} M^j v
__device__ float d_part[16 * NS2];        // split-K partials (16.8 MB, reused)
__device__ unsigned d_slots[2048];        // grid-barrier slots (memset each launch)

// ---------------- small helpers (precompute, unchanged from R12) ----------------
__global__ void k_tpose(const float* __restrict__ A, float* __restrict__ Lt) {
    int idx = blockIdx.x * blockDim.x + threadIdx.x;
    if (idx < NS2) {
        int i = idx >> 9, j = idx & 511;
        Lt[idx] = DTC * A[j * NS + i];
    }
}

__global__ void k_gh(const float* __restrict__ B, const float* __restrict__ Q,
                     float* __restrict__ g, float* __restrict__ h) {
    int i = blockIdx.x * blockDim.x + threadIdx.x;
    if (i < NS) {
        g[i] = B[i * 9];
        float s = 0.f;
#pragma unroll
        for (int m = 0; m < 8; m++) s += B[i * 9 + 1 + m] * Q[m];
        h[i] = s;
    }
}

__global__ void k_matvec2(const float* __restrict__ A,
                          const float* __restrict__ x1, const float* __restrict__ x2,
                          float* __restrict__ y1, float* __restrict__ y2, float scale) {
    __shared__ float red1[128], red2[128];
    int row = blockIdx.x;
    float s1 = 0.f, s2 = 0.f;
    for (int j = threadIdx.x; j < NS; j += 128) {
        float a = A[row * NS + j];
        s1 += a * x1[j];
        s2 += a * x2[j];
    }
    red1[threadIdx.x] = s1; red2[threadIdx.x] = s2;
    __syncthreads();
    for (int st = 64; st > 0; st >>= 1) {
        if (threadIdx.x < st) {
            red1[threadIdx.x] += red1[threadIdx.x + st];
            red2[threadIdx.x] += red2[threadIdx.x + st];
        }
        __syncthreads();
    }
    if (threadIdx.x == 0) { y1[row] = scale * red1[0]; y2[row] = scale * red2[0]; }
}

__global__ void k_combine(const float* __restrict__ vec, float* __restrict__ vw) {
    int i = blockIdx.x * blockDim.x + threadIdx.x;
    if (i >= NS) return;
    const float G   = vec[0 * NS + i], H   = vec[1 * NS + i];
    const float LG  = vec[2 * NS + i], L2G = vec[3 * NS + i], L3G = vec[4 * NS + i];
    const float LH  = vec[5 * NS + i], L2H = vec[6 * NS + i], L3H = vec[7 * NS + i];
    const float c = DTC / 8.0f;
    vw[0 * NS + i] = c * (G + LG + (L2G + L3G) * (1.0f / 3.0f));
    vw[1 * NS + i] = c * (3.0f * G + 2.0f * LG + L2G);
    vw[2 * NS + i] = c * (3.0f * G + LG);
    vw[3 * NS + i] = c * G;
    vw[4 * NS + i] = DTC * (H + 0.5f * LH + L2H * (1.0f / 6.0f) + L3H * (1.0f / 24.0f));
}

__global__ void k_prep1(const float* __restrict__ Lt, const float* __restrict__ G1,
                        float* __restrict__ H, float* __restrict__ base) {
    int idx = blockIdx.x * blockDim.x + threadIdx.x;
    if (idx < NS2) {
        int i = idx >> 9, j = idx & 511;
        float l = Lt[idx], g = G1[idx];
        H[idx]    = l * (1.0f / 6.0f) + g * (1.0f / 24.0f);
        base[idx] = l + 0.5f * g + (i == j ? 1.0f : 0.0f);
    }
}

__global__ void __launch_bounds__(128) k_gsk(
    const float* __restrict__ A, const float* __restrict__ B, float* __restrict__ part)
{
    __shared__ float As[16][36];
    __shared__ float Bs[16][68];
    const int t  = threadIdx.x;
    const int tx = t & 7, ty = t >> 3;
    const int r0 = blockIdx.y * 32, c0 = blockIdx.x * 64;
    const int kb = blockIdx.z * 128;

    const int ar = t >> 2, ac4 = (t & 3) * 4;
    const int br = t >> 4, bc4 = (t & 15) * 4;

    unsigned long long acc[2][4];
#pragma unroll
    for (int m = 0; m < 2; m++)
#pragma unroll
        for (int p = 0; p < 4; p++) acc[m][p] = 0ull;

    float4 av = *(const float4*)(A + (size_t)(r0 + ar) * NS + kb + ac4);
    float4 b0 = *(const float4*)(B + (size_t)(kb + br) * NS + c0 + bc4);
    float4 b1 = *(const float4*)(B + (size_t)(kb + br + 8) * NS + c0 + bc4);

    for (int it = 0; it < 8; ++it) {
        As[ac4 + 0][ar] = av.x; As[ac4 + 1][ar] = av.y;
        As[ac4 + 2][ar] = av.z; As[ac4 + 3][ar] = av.w;
        *(float4*)&Bs[br][bc4]     = b0;
        *(float4*)&Bs[br + 8][bc4] = b1;
        __syncthreads();
        if (it < 7) {
            const int k0 = kb + (it + 1) * 16;
            av = *(const float4*)(A + (size_t)(r0 + ar) * NS + k0 + ac4);
            b0 = *(const float4*)(B + (size_t)(k0 + br) * NS + c0 + bc4);
            b1 = *(const float4*)(B + (size_t)(k0 + br + 8) * NS + c0 + bc4);
        }
#pragma unroll
        for (int kk = 0; kk < 16; ++kk) {
            float a0 = As[kk][ty * 2 + 0];
            float a1 = As[kk][ty * 2 + 1];
            ulonglong2 bp0 = *(const ulonglong2*)&Bs[kk][tx * 8];
            ulonglong2 bp1 = *(const ulonglong2*)&Bs[kk][tx * 8 + 4];
            unsigned long long bv[4] = {bp0.x, bp0.y, bp1.x, bp1.y};
            unsigned long long av0, av1;
            asm("mov.b64 %0, {%1, %1};" : "=l"(av0) : "f"(a0));
            asm("mov.b64 %0, {%1, %1};" : "=l"(av1) : "f"(a1));
#pragma unroll
            for (int p = 0; p < 4; p++) {
                asm("fma.rn.f32x2 %0, %1, %2, %0;" : "+l"(acc[0][p]) : "l"(av0), "l"(bv[p]));
                asm("fma.rn.f32x2 %0, %1, %2, %0;" : "+l"(acc[1][p]) : "l"(av1), "l"(bv[p]));
            }
        }
        __syncthreads();
    }
    float* po = part + (size_t)blockIdx.z * NS2;
#pragma unroll
    for (int m = 0; m < 2; m++) {
        const int row = r0 + ty * 2 + m;
#pragma unroll
        for (int p = 0; p < 4; p++) {
            float lo, hi;
            asm("mov.b64 {%0, %1}, %2;" : "=f"(lo), "=f"(hi) : "l"(acc[m][p]));
            int col = c0 + tx * 8 + 2 * p;
            po[(size_t)row * NS + col]     = lo;
            po[(size_t)row * NS + col + 1] = hi;
        }
    }
}

__global__ void __launch_bounds__(128) k_gskz(
    float* __restrict__ Tb, float* __restrict__ part,
    int a0, int a1, int a2, int a3, int b0s, int b1s, int b2s, int b3s)
{
    const int item = blockIdx.z >> 2;
    const int ks   = blockIdx.z & 3;
    const int asl  = (item == 0) ? a0 : (item == 1) ? a1 : (item == 2) ? a2 : a3;
    const int bsl  = (item == 0) ? b0s : (item == 1) ? b1s : (item == 2) ? b2s : b3s;
    const float* A = Tb + (size_t)asl * NS2;
    const float* B = Tb + (size_t)bsl * NS2;

    __shared__ float As[16][36];
    __shared__ float Bs[16][68];
    const int t  = threadIdx.x;
    const int tx = t & 7, ty = t >> 3;
    const int r0 = blockIdx.y * 32, c0 = blockIdx.x * 64;
    const int kb = ks * 128;

    const int ar = t >> 2, ac4 = (t & 3) * 4;
    const int br = t >> 4, bc4 = (t & 15) * 4;

    unsigned long long acc[2][4];
#pragma unroll
    for (int m = 0; m < 2; m++)
#pragma unroll
        for (int p = 0; p < 4; p++) acc[m][p] = 0ull;

    float4 av = *(const float4*)(A + (size_t)(r0 + ar) * NS + kb + ac4);
    float4 b0 = *(const float4*)(B + (size_t)(kb + br) * NS + c0 + bc4);
    float4 b1 = *(const float4*)(B + (size_t)(kb + br + 8) * NS + c0 + bc4);

    for (int it = 0; it < 8; ++it) {
        As[ac4 + 0][ar] = av.x; As[ac4 + 1][ar] = av.y;
        As[ac4 + 2][ar] = av.z; As[ac4 + 3][ar] = av.w;
        *(float4*)&Bs[br][bc4]     = b0;
        *(float4*)&Bs[br + 8][bc4] = b1;
        __syncthreads();
        if (it < 7) {
            const int k0 = kb + (it + 1) * 16;
            av = *(const float4*)(A + (size_t)(r0 + ar) * NS + k0 + ac4);
            b0 = *(const float4*)(B + (size_t)(k0 + br) * NS + c0 + bc4);
            b1 = *(const float4*)(B + (size_t)(k0 + br + 8) * NS + c0 + bc4);
        }
#pragma unroll
        for (int kk = 0; kk < 16; ++kk) {
            float a0f = As[kk][ty * 2 + 0];
            float a1f = As[kk][ty * 2 + 1];
            ulonglong2 bp0 = *(const ulonglong2*)&Bs[kk][tx * 8];
            ulonglong2 bp1 = *(const ulonglong2*)&Bs[kk][tx * 8 + 4];
            unsigned long long bv[4] = {bp0.x, bp0.y, bp1.x, bp1.y};
            unsigned long long av0, av1;
            asm("mov.b64 %0, {%1, %1};" : "=l"(av0) : "f"(a0f));
            asm("mov.b64 %0, {%1, %1};" : "=l"(av1) : "f"(a1f));
#pragma unroll
            for (int p = 0; p < 4; p++) {
                asm("fma.rn.f32x2 %0, %1, %2, %0;" : "+l"(acc[0][p]) : "l"(av0), "l"(bv[p]));
                asm("fma.rn.f32x2 %0, %1, %2, %0;" : "+l"(acc[1][p]) : "l"(av1), "l"(bv[p]));
            }
        }
        __syncthreads();
    }
    float* po = part + (size_t)(item * 4 + ks) * NS2;
#pragma unroll
    for (int m = 0; m < 2; m++) {
        const int row = r0 + ty * 2 + m;
#pragma unroll
        for (int p = 0; p < 4; p++) {
            float lo, hi;
            asm("mov.b64 {%0, %1}, %2;" : "=f"(lo), "=f"(hi) : "l"(acc[m][p]));
            int col = c0 + tx * 8 + 2 * p;
            po[(size_t)row * NS + col]     = lo;
            po[(size_t)row * NS + col + 1] = hi;
        }
    }
}

__global__ void k_gred(float* __restrict__ C, const float* __restrict__ part,
                       const float* __restrict__ base) {
    int idx = blockIdx.x * 256 + threadIdx.x;
    size_t o = (size_t)idx * 4;
    float4 p0 = *(const float4*)(part + 0 * (size_t)NS2 + o);
    float4 p1 = *(const float4*)(part + 1 * (size_t)NS2 + o);
    float4 p2 = *(const float4*)(part + 2 * (size_t)NS2 + o);
    float4 p3 = *(const float4*)(part + 3 * (size_t)NS2 + o);
    float4 b = base ? *(const float4*)(base + o) : make_float4(0.f, 0.f, 0.f, 0.f);
    float4 r;
    r.x = b.x + (p0.x + p1.x) + (p2.x + p3.x);
    r.y = b.y + (p0.y + p1.y) + (p2.y + p3.y);
    r.z = b.z + (p0.z + p1.z) + (p2.z + p3.z);
    r.w = b.w + (p0.w + p1.w) + (p2.w + p3.w);
    *(float4*)(C + o) = r;
}

__global__ void k_gredz(float* __restrict__ Tb, const float* __restrict__ part,
                        int d0, int d1, int d2, int d3) {
    const int item = blockIdx.y;
    const int dsl  = (item == 0) ? d0 : (item == 1) ? d1 : (item == 2) ? d2 : d3;
    int idx = blockIdx.x * 256 + threadIdx.x;
    size_t o = (size_t)idx * 4;
    const float* p = part + (size_t)(item * 4) * NS2;
    float4 p0 = *(const float4*)(p + 0 * (size_t)NS2 + o);
    float4 p1 = *(const float4*)(p + 1 * (size_t)NS2 + o);
    float4 p2 = *(const float4*)(p + 2 * (size_t)NS2 + o);
    float4 p3 = *(const float4*)(p + 3 * (size_t)NS2 + o);
    float4 r;
    r.x = (p0.x + p1.x) + (p2.x + p3.x);
    r.y = (p0.y + p1.y) + (p2.y + p3.y);
    r.z = (p0.z + p1.z) + (p2.z + p3.z);
    r.w = (p0.w + p1.w) + (p2.w + p3.w);
    *(float4*)(Tb + (size_t)dsl * NS2 + o) = r;
}

__global__ void k_vw(const float* __restrict__ Tb, float* __restrict__ vw) {
    const int j = blockIdx.z + 1;
    const float* T = Tb + (size_t)j * NS2;
    const int c = blockIdx.x * 256 + threadIdx.x;

    __shared__ float v0s[5 * NS];
    for (int i = threadIdx.x; i < 5 * NS; i += 256) v0s[i] = vw[i];
    __syncthreads();

    float acc0 = 0.f, acc1 = 0.f, acc2 = 0.f, acc3 = 0.f, acc4 = 0.f;
    for (int k = 0; k < NS; ++k) {
        float tk = T[(size_t)k * NS + c];
        acc0 += v0s[0 * NS + k] * tk;
        acc1 += v0s[1 * NS + k] * tk;
        acc2 += v0s[2 * NS + k] * tk;
        acc3 += v0s[3 * NS + k] * tk;
        acc4 += v0s[4 * NS + k] * tk;
    }
    float* o = vw + (size_t)j * 5 * NS;
    o[0 * NS + c] = acc0; o[1 * NS + c] = acc1; o[2 * NS + c] = acc2;
    o[3 * NS + c] = acc3; o[4 * NS + c] = acc4;
}

__global__ void k_cv(const float* __restrict__ vw, float* __restrict__ cv) {
    int c = blockIdx.x * 256 + threadIdx.x;
    if (c >= NS) return;
    float acc = 0.f;
    for (int j = 0; j < RAD; ++j) {
        acc += vw[((size_t)j * 5 + 4) * NS + c];
        cv[(size_t)j * NS + c] = acc;
    }
}

// ---------------- persistent mega-kernel: buildE0 + anchor BK + fill ----------------
__device__ __forceinline__ float dev_interp(const float* __restrict__ Tt,
                                            const float* __restrict__ Tv, float tq) {
    if (tq <= Tt[0])      return Tv[0];
    if (tq >= Tt[ND - 1]) return Tv[ND - 1];
    int lo = 0, hi = ND - 1;
    while (hi - lo > 1) {
        int mid = (lo + hi) >> 1;
        if (Tt[mid] <= tq) lo = mid; else hi = mid;
    }
    float x0 = Tt[lo], x1 = Tt[lo + 1];
    return Tv[lo] + (tq - x0) * (Tv[lo + 1] - Tv[lo]) / (x1 - x0);
}

struct SMem {
    float As[16][132];
    float Bs[16][68];
    float s[15][4];
};

// software grid barrier (slot-per-block; no atomic hotspot)
__device__ __forceinline__ void gbar(unsigned gen) {
    __syncthreads();
    if (threadIdx.x == 0) {
        __threadfence();
        asm volatile("st.volatile.global.u32 [%0], %1;"
                     :: "l"(&d_slots[blockIdx.x]), "r"(gen) : "memory");
    }
    const int NB = gridDim.x;
    for (int s = threadIdx.x; s < NB; s += 128) {
        unsigned v;
        do {
            asm volatile("ld.volatile.global.u32 %0, [%1];"
                         : "=r"(v) : "l"(&d_slots[s]) : "memory");
        } while (v < gen);
    }
    __syncthreads();
    __threadfence();   // gpu-scope: also invalidates L1 (stale-line safety)
}

// E0 group body (rows 8g..8g+7), 128 threads
__device__ __forceinline__ void e0_body(
    int g, int t, const float* __restrict__ Tt, const float* __restrict__ Tv,
    const float* __restrict__ iv, const float* __restrict__ vw,
    const float* __restrict__ cv, float* __restrict__ E0, SMem& sm)
{
    const int d0 = 8 * g - 8;
    __syncthreads();                      // protect sm.s reuse across groups
    if (t < 60) {
        int jj = t >> 2, ii = t & 3;
        int d = d0 + jj;
        if (d >= 0) {
            float tq = (float)d * DTC + (float)ii * 10.0f;
            sm.s[jj][ii] = dev_interp(Tt, Tv, tq);
        }
    }
    __syncthreads();
#pragma unroll 1
    for (int q = 0; q < 8; ++q) {
        const int n = 8 * g + q;
        float* row = E0 + (size_t)n * NS;
        if (n == 0) {
            for (int i = t; i < NS; i += 128) row[i] = iv[i];
            continue;
        }
        const int p = ((n - 1) & 7) + 1;
        const float* cvp = cv + (size_t)(p - 1) * NS;
        for (int i = t; i < NS; i += 128) {
            float acc = cvp[i];
            for (int jj = 0; jj < p; ++jj) {
                const float* sj = sm.s[q + 7 - jj];
                const float* base = vw + (size_t)jj * 5 * NS;
                acc += sj[0] * base[i]          + sj[1] * base[NS + i]
                     + sj[2] * base[2 * NS + i] + sj[3] * base[3 * NS + i];
            }
            row[i] = acc;
        }
    }
}

// anchor BK split-K sk body (verbatim R12 k_bk_sk with decoded r0/c0/kb)
__device__ __forceinline__ void bk_sk_body(
    const float* __restrict__ V, const float* __restrict__ W,
    float* __restrict__ part, int S, int aoff, int cnt,
    int r0, int c0, int kb, int zidx, int t, SMem& sm)
{
    float (*As)[132] = sm.As;
    float (*Bs)[68]  = sm.Bs;
    const int tx = t & 7;
    const int ty = t >> 3;

    const int  ar  = t >> 2;
    const int  ac4 = (t & 3) * 4;
    long gr[4]; bool v[4];
#pragma unroll
    for (int g = 0; g < 4; g++) {
        int lo = r0 + ar + 32 * g;
        v[g]  = lo < cnt;
        gr[g] = (long)lo * S + aoff;
    }

    const int br  = t >> 4;
    const int bc4 = (t & 15) * 4;

    unsigned long long acc[8][4];
#pragma unroll
    for (int m = 0; m < 8; m++)
#pragma unroll
        for (int p = 0; p < 4; p++) acc[m][p] = 0ull;

    const float4 f4z = make_float4(0.f, 0.f, 0.f, 0.f);
    float4 av[4], b0, b1;
#pragma unroll
    for (int g = 0; g < 4; g++)
        av[g] = v[g] ? *(const float4*)(V + gr[g] * NS + kb + ac4) : f4z;
    b0 = *(const float4*)(W + (size_t)(kb + br) * NS + c0 + bc4);
    b1 = *(const float4*)(W + (size_t)(kb + br + 8) * NS + c0 + bc4);

    for (int it = 0; it < 8; ++it) {
#pragma unroll
        for (int g = 0; g < 4; g++) {
            As[ac4 + 0][ar + 32 * g] = av[g].x;
            As[ac4 + 1][ar + 32 * g] = av[g].y;
            As[ac4 + 2][ar + 32 * g] = av[g].z;
            As[ac4 + 3][ar + 32 * g] = av[g].w;
        }
        *(float4*)&Bs[br][bc4]     = b0;
        *(float4*)&Bs[br + 8][bc4] = b1;
        __syncthreads();

        if (it < 7) {
            const int k0 = kb + (it + 1) * 16;
#pragma unroll
            for (int g = 0; g < 4; g++)
                av[g] = v[g] ? *(const float4*)(V + gr[g] * NS + k0 + ac4) : f4z;
            b0 = *(const float4*)(W + (size_t)(k0 + br) * NS + c0 + bc4);
            b1 = *(const float4*)(W + (size_t)(k0 + br + 8) * NS + c0 + bc4);
        }

#pragma unroll
        for (int kk = 0; kk < 16; ++kk) {
            float a[8];
            *(float4*)&a[0] = *(const float4*)&As[kk][ty * 8];
            *(float4*)&a[4] = *(const float4*)&As[kk][ty * 8 + 4];
            ulonglong2 bp0 = *(const ulonglong2*)&Bs[kk][tx * 8];
            ulonglong2 bp1 = *(const ulonglong2*)&Bs[kk][tx * 8 + 4];
            unsigned long long bv[4] = {bp0.x, bp0.y, bp1.x, bp1.y};
#pragma unroll
            for (int m = 0; m < 8; m++) {
                unsigned long long avv;
                asm("mov.b64 %0, {%1, %1};" : "=l"(avv) : "f"(a[m]));
#pragma unroll
                for (int p = 0; p < 4; p++)
                    asm("fma.rn.f32x2 %0, %1, %2, %0;"
                        : "+l"(acc[m][p]) : "l"(avv), "l"(bv[p]));
            }
        }
        __syncthreads();
    }

#pragma unroll
    for (int m = 0; m < 8; m++) {
        const int r = r0 + ty * 8 + m;
        if (r < cnt) {
            float c[8];
#pragma unroll
            for (int p = 0; p < 4; p++)
                asm("mov.b64 {%0, %1}, %2;"
                    : "=f"(c[2 * p]), "=f"(c[2 * p + 1]) : "l"(acc[m][p]));
            float* prow = part + ((size_t)zidx * SKROWS + r) * NS + c0 + tx * 8;
            *(float4*)prow       = make_float4(c[0], c[1], c[2], c[3]);
            *(float4*)(prow + 4) = make_float4(c[4], c[5], c[6], c[7]);
        }
    }
}

// fill body (verbatim R12 k_fillz with decoded q/r0/c0)
__device__ __forceinline__ void fill_body(
    float* __restrict__ V, const float* __restrict__ Tb,
    int q, int r0, int c0, int cnt, int t, SMem& sm)
{
    const float* W = Tb + (size_t)q * NS2;
    float (*As)[132] = sm.As;
    float (*Bs)[68]  = sm.Bs;
    const int tx = t & 7;
    const int ty = t >> 3;

    const int  ar  = t >> 2;
    const int  ac4 = (t & 3) * 4;
    long gr[4]; bool v[4];
#pragma unroll
    for (int g = 0; g < 4; g++) {
        int lo = r0 + ar + 32 * g;
        v[g]  = lo < cnt;
        gr[g] = (long)lo * RAD;
    }

    const int br  = t >> 4;
    const int bc4 = (t & 15) * 4;

    unsigned long long acc[8][4];
#pragma unroll
    for (int m = 0; m < 8; m++)
#pragma unroll
        for (int p = 0; p < 4; p++) acc[m][p] = 0ull;

    const float4 f4z = make_float4(0.f, 0.f, 0.f, 0.f);
    float4 av[4], b0, b1;
#pragma unroll
    for (int g = 0; g < 4; g++)
        av[g] = v[g] ? *(const float4*)(V + gr[g] * NS + ac4) : f4z;
    b0 = *(const float4*)(W + (size_t)br * NS + c0 + bc4);
    b1 = *(const float4*)(W + (size_t)(br + 8) * NS + c0 + bc4);

    for (int it = 0; it < 32; ++it) {
#pragma unroll
        for (int g = 0; g < 4; g++) {
            As[ac4 + 0][ar + 32 * g] = av[g].x;
            As[ac4 + 1][ar + 32 * g] = av[g].y;
            As[ac4 + 2][ar + 32 * g] = av[g].z;
            As[ac4 + 3][ar + 32 * g] = av[g].w;
        }
        *(float4*)&Bs[br][bc4]     = b0;
        *(float4*)&Bs[br + 8][bc4] = b1;
        __syncthreads();

        if (it < 31) {
            const int k0 = (it + 1) * 16;
#pragma unroll
            for (int g = 0; g < 4; g++)
                av[g] = v[g] ? *(const float4*)(V + gr[g] * NS + k0 + ac4) : f4z;
            b0 = *(const float4*)(W + (size_t)(k0 + br) * NS + c0 + bc4);
            b1 = *(const float4*)(W + (size_t)(k0 + br + 8) * NS + c0 + bc4);
        }

#pragma unroll
        for (int kk = 0; kk < 16; ++kk) {
            float a[8];
            *(float4*)&a[0] = *(const float4*)&As[kk][ty * 8];
            *(float4*)&a[4] = *(const float4*)&As[kk][ty * 8 + 4];
            ulonglong2 bp0 = *(const ulonglong2*)&Bs[kk][tx * 8];
            ulonglong2 bp1 = *(const ulonglong2*)&Bs[kk][tx * 8 + 4];
            unsigned long long bv[4] = {bp0.x, bp0.y, bp1.x, bp1.y};
#pragma unroll
            for (int m = 0; m < 8; m++) {
                unsigned long long avv;
                asm("mov.b64 %0, {%1, %1};" : "=l"(avv) : "f"(a[m]));
#pragma unroll
                for (int p = 0; p < 4; p++)
                    asm("fma.rn.f32x2 %0, %1, %2, %0;"
                        : "+l"(acc[m][p]) : "l"(avv), "l"(bv[p]));
            }
        }
        __syncthreads();
    }

#pragma unroll
    for (int m = 0; m < 8; m++) {
        const int r = r0 + ty * 8 + m;
        if (r < cnt) {
            const long dr = (long)r * RAD + q;
            float* erow = V + dr * NS + c0 + tx * 8;
            float4 e0 = *(const float4*)erow;
            float4 e1 = *(const float4*)(erow + 4);
            float c[8];
#pragma unroll
            for (int p = 0; p < 4; p++)
                asm("mov.b64 {%0, %1}, %2;"
                    : "=f"(c[2 * p]), "=f"(c[2 * p + 1]) : "l"(acc[m][p]));
            float4 o0 = make_float4(c[0] + e0.x, c[1] + e0.y, c[2] + e0.z, c[3] + e0.w);
            float4 o1 = make_float4(c[4] + e1.x, c[5] + e1.y, c[6] + e1.z, c[7] + e1.w);
            *(float4*)erow       = o0;
            *(float4*)(erow + 4) = o1;
        }
    }
}

__global__ void __launch_bounds__(128, 4) k_mega(
    const float* __restrict__ Tt, const float* __restrict__ Tv,
    const float* __restrict__ iv, const float* __restrict__ vw,
    const float* __restrict__ cv, const float* __restrict__ Tb,
    float* __restrict__ V, float* __restrict__ part)
{
    __shared__ SMem sm;
    const int bid = blockIdx.x, NB = gridDim.x, t = threadIdx.x;
    unsigned gen = 0;

    // ---- phase 0: build E0 (within-group-of-8 prefixes)
    for (int g = bid; g < NANCH; g += NB)
        e0_body(g, t, Tt, Tv, iv, vw, cv, V, sm);
    gbar(++gen);

    // ---- phases 1..20: anchor Brent-Kung (10 levels, sk + red each)
#pragma unroll 1
    for (int lv = 0; lv < 10; ++lv) {
        const bool up = lv < 5;
        const int j  = up ? lv : 9 - lv;
        const int Sa = 1 << (j + 1);
        int cnt, aoffA, boffA;
        if (up) {
            cnt = NANCH >> (j + 1);
            aoffA = (1 << j) - 1;
            boffA = Sa - 1;
        } else {
            boffA = Sa - 1 + (1 << j);
            cnt = (NANCH - 1 - boffA) / Sa + 1;
            aoffA = Sa - 1;
        }
        const int Sm   = RAD * Sa;
        const int aoff = RAD * aoffA;
        const int boff = RAD * boffA;
        const float* W = Tb + (size_t)(8 + j) * NS2;
        const int njobs = ((cnt + 127) >> 7) * 32;

        for (int job = bid; job < njobs; job += NB) {
            const int r0 = (job >> 5) << 7;
            const int rest = job & 31;
            bk_sk_body(V, W, part, Sm, aoff, cnt,
                       r0, (rest >> 2) * 64, (rest & 3) * 128, rest & 3, t, sm);
        }
        gbar(++gen);

        const int total = cnt * 128;     // float4 units
        for (int idx = bid * 128 + t; idx < total; idx += NB * 128) {
            const int r  = idx >> 7;
            const int c4 = (idx & 127) << 2;
            float4 p0 = *(const float4*)(part + ((size_t)0 * SKROWS + r) * NS + c4);
            float4 p1 = *(const float4*)(part + ((size_t)1 * SKROWS + r) * NS + c4);
            float4 p2 = *(const float4*)(part + ((size_t)2 * SKROWS + r) * NS + c4);
            float4 p3 = *(const float4*)(part + ((size_t)3 * SKROWS + r) * NS + c4);
            float* dst = V + ((size_t)r * Sm + boff) * NS + c4;
            float4 d = *(const float4*)dst;
            d.x += (p0.x + p1.x) + (p2.x + p3.x);
            d.y += (p0.y + p1.y) + (p2.y + p3.y);
            d.z += (p0.z + p1.z) + (p2.z + p3.z);
            d.w += (p0.w + p1.w) + (p2.w + p3.w);
            *(float4*)dst = d;
        }
        gbar(++gen);
    }

    // ---- final phase: flat fill (q = 1..7), 1120 jobs
    const int fjobs = ((NANCH + 127) >> 7) * 8 * (RAD - 1);   // 20*8*7
    for (int job = bid; job < fjobs; job += NB) {
        const int q = job / 160 + 1;
        const int rest = job % 160;
        fill_body(V, Tb, q, (rest >> 3) << 7, (rest & 7) * 64, NANCH, t, sm);
    }
}

// ---------------- host orchestration (graph-capturable, alloc-free) ----------------
extern "C" void kernel_launch(void* const* d_in, const int* in_sizes, int n_in,
                              void* d_out, int out_size) {
    const float* A  = (const float*)d_in[0];
    const float* Bm = (const float*)d_in[1];
    const float* Q  = (const float*)d_in[2];
    const float* Tt = (const float*)d_in[3];
    const float* Tv = (const float*)d_in[4];
    const float* iv = (const float*)d_in[5];
    float* out = (float*)d_out;

    float *Lt, *G1, *G2, *Tb, *vec, *vw, *cv, *part;
    unsigned* slots;
    cudaGetSymbolAddress((void**)&Lt,    d_Lt);
    cudaGetSymbolAddress((void**)&G1,    d_G1);
    cudaGetSymbolAddress((void**)&G2,    d_G2);
    cudaGetSymbolAddress((void**)&Tb,    d_T);
    cudaGetSymbolAddress((void**)&vec,   d_vec);
    cudaGetSymbolAddress((void**)&vw,    d_vw);
    cudaGetSymbolAddress((void**)&cv,    d_cv);
    cudaGetSymbolAddress((void**)&part,  d_part);
    cudaGetSymbolAddress((void**)&slots, d_slots);

    // Lt = (dt*A)^T
    k_tpose<<<1024, 256>>>(A, Lt);

    // forcing vectors w1..w4, v  (into vw[0])
    k_gh<<<2, 256>>>(Bm, Q, vec + 0 * NS, vec + 1 * NS);
    k_matvec2<<<512, 128>>>(A, vec + 0 * NS, vec + 1 * NS, vec + 2 * NS, vec + 5 * NS, DTC);
    k_matvec2<<<512, 128>>>(A, vec + 2 * NS, vec + 5 * NS, vec + 3 * NS, vec + 6 * NS, DTC);
    k_matvec2<<<512, 128>>>(A, vec + 3 * NS, vec + 6 * NS, vec + 4 * NS, vec + 7 * NS, DTC);
    k_combine<<<2, 256>>>(vec, vw);

    const dim3 gsk(8, 16, 4);
    const int RB = NS2 / 4 / 256;

    // G1 = Lt^2 ; T1 = (I + Lt + G1/2) + G1 @ (Lt/6 + G1/24)
    k_gsk<<<gsk, 128>>>(Lt, Lt, part);
    k_gred<<<RB, 256>>>(G1, part, nullptr);
    k_prep1<<<1024, 256>>>(Lt, G1, G2, Tb + 0 * (size_t)NS2);
    k_gsk<<<gsk, 128>>>(G1, G2, part);
    k_gred<<<RB, 256>>>(Tb + 1 * (size_t)NS2, part, Tb + 0 * (size_t)NS2);

    // T2 ; {T3,T4} ; {T5..T8} ; T16 ; T32 ; T64 ; T128
    k_gsk<<<gsk, 128>>>(Tb + 1 * (size_t)NS2, Tb + 1 * (size_t)NS2, part);
    k_gred<<<RB, 256>>>(Tb + 2 * (size_t)NS2, part, nullptr);

    k_gskz<<<dim3(8, 16, 8), 128>>>(Tb, part, 1, 2, 0, 0, 2, 2, 0, 0);
    k_gredz<<<dim3(RB, 2), 256>>>(Tb, part, 3, 4, 0, 0);

    k_gskz<<<dim3(8, 16, 16), 128>>>(Tb, part, 1, 2, 3, 4, 4, 4, 4, 4);
    k_gredz<<<dim3(RB, 4), 256>>>(Tb, part, 5, 6, 7, 8);

    for (int s = 8; s <= 11; ++s) {
        k_gsk<<<gsk, 128>>>(Tb + (size_t)s * NS2, Tb + (size_t)s * NS2, part);
        k_gred<<<RB, 256>>>(Tb + (size_t)(s + 1) * NS2, part, nullptr);
    }

    // vw[j] = [w,v] @ T_j (j=1..7) ; cv cumsums
    k_vw<<<dim3(2, 1, 7), 256>>>(Tb, vw);
    k_cv<<<2, 256>>>(vw, cv);

    // ---- persistent kernel: E0 + anchor BK + fill (one launch)
    cudaMemsetAsync(slots, 0, 2048 * sizeof(unsigned), 0);
    int dev = 0;
    cudaGetDevice(&dev);
    int sms = 0;
    cudaDeviceGetAttribute(&sms, cudaDevAttrMultiProcessorCount, dev);
    int occ = 0;
    cudaOccupancyMaxActiveBlocksPerMultiprocessor(&occ, k_mega, 128, 0);
    if (occ < 1) occ = 1;
    long NB = (long)sms * occ;
    if (NB > 2048) NB = 2048;
    k_mega<<<(int)NB, 128>>>(Tt, Tv, iv, vw, cv, Tb, out, part);
    // result in `out`
}

// round 14
// speedup vs baseline: 1.1881x; 1.1881x over previous
#include <cuda_runtime.h>

#define NS   512
#define NS2  (NS * NS)
#define TN   20000
#define ND   2000
#define DTC  30.0f
#define RAD  8
#define NANCH 2500      // TN / RAD
#define NSUP 313        // supers s=0..312 (rows 64s)
#define SKR  320        // small-partial row stride

// ---------------- static scratch (no allocations allowed) ----------------
__device__ float d_Lt[NS2];
__device__ float d_G1[NS2];
__device__ float d_G2[NS2];
// T slots: 0 base ; 1..8 T1..T8 ; 9 T16 ; 10 T24 ; 11 T32 ; 12 T40 ; 13 T48 ; 14 T56 ; 15 T64 ; 16 T128 ; 17 T192
__device__ float d_T[18][NS2];
__device__ float d_vec[8 * NS];
__device__ float d_vw[64 * 5 * NS];       // vw[j] = M^j [w1..w4, v], j=0..63
__device__ float d_cv[64 * NS];           // cv[p-1] = sum_{j<p} M^j v
__device__ float d_part[20 * NS2];        // partials (21 MB, reused)

// ---------------- small helpers ----------------
__global__ void k_tpose(const float* __restrict__ A, float* __restrict__ Lt) {
    int idx = blockIdx.x * blockDim.x + threadIdx.x;
    if (idx < NS2) {
        int i = idx >> 9, j = idx & 511;
        Lt[idx] = DTC * A[j * NS + i];
    }
}

__global__ void k_gh(const float* __restrict__ B, const float* __restrict__ Q,
                     float* __restrict__ g, float* __restrict__ h) {
    int i = blockIdx.x * blockDim.x + threadIdx.x;
    if (i < NS) {
        g[i] = B[i * 9];
        float s = 0.f;
#pragma unroll
        for (int m = 0; m < 8; m++) s += B[i * 9 + 1 + m] * Q[m];
        h[i] = s;
    }
}

__global__ void k_matvec2(const float* __restrict__ A,
                          const float* __restrict__ x1, const float* __restrict__ x2,
                          float* __restrict__ y1, float* __restrict__ y2, float scale) {
    __shared__ float red1[128], red2[128];
    int row = blockIdx.x;
    float s1 = 0.f, s2 = 0.f;
    for (int j = threadIdx.x; j < NS; j += 128) {
        float a = A[row * NS + j];
        s1 += a * x1[j];
        s2 += a * x2[j];
    }
    red1[threadIdx.x] = s1; red2[threadIdx.x] = s2;
    __syncthreads();
    for (int st = 64; st > 0; st >>= 1) {
        if (threadIdx.x < st) {
            red1[threadIdx.x] += red1[threadIdx.x + st];
            red2[threadIdx.x] += red2[threadIdx.x + st];
        }
        __syncthreads();
    }
    if (threadIdx.x == 0) { y1[row] = scale * red1[0]; y2[row] = scale * red2[0]; }
}

__global__ void k_combine(const float* __restrict__ vec, float* __restrict__ vw) {
    int i = blockIdx.x * blockDim.x + threadIdx.x;
    if (i >= NS) return;
    const float G   = vec[0 * NS + i], H   = vec[1 * NS + i];
    const float LG  = vec[2 * NS + i], L2G = vec[3 * NS + i], L3G = vec[4 * NS + i];
    const float LH  = vec[5 * NS + i], L2H = vec[6 * NS + i], L3H = vec[7 * NS + i];
    const float c = DTC / 8.0f;
    vw[0 * NS + i] = c * (G + LG + (L2G + L3G) * (1.0f / 3.0f));
    vw[1 * NS + i] = c * (3.0f * G + 2.0f * LG + L2G);
    vw[2 * NS + i] = c * (3.0f * G + LG);
    vw[3 * NS + i] = c * G;
    vw[4 * NS + i] = DTC * (H + 0.5f * LH + L2H * (1.0f / 6.0f) + L3H * (1.0f / 24.0f));
}

__global__ void k_prep1(const float* __restrict__ Lt, const float* __restrict__ G1,
                        float* __restrict__ H, float* __restrict__ base) {
    int idx = blockIdx.x * blockDim.x + threadIdx.x;
    if (idx < NS2) {
        int i = idx >> 9, j = idx & 511;
        float l = Lt[idx], g = G1[idx];
        H[idx]    = l * (1.0f / 6.0f) + g * (1.0f / 24.0f);
        base[idx] = l + 0.5f * g + (i == j ? 1.0f : 0.0f);
    }
}

// ---------------- split-K 512^3 GEMM partials ----------------
__global__ void __launch_bounds__(128) k_gsk(
    const float* __restrict__ A, const float* __restrict__ B, float* __restrict__ part)
{
    __shared__ float As[16][36];
    __shared__ float Bs[16][68];
    const int t  = threadIdx.x;
    const int tx = t & 7, ty = t >> 3;
    const int r0 = blockIdx.y * 32, c0 = blockIdx.x * 64;
    const int kb = blockIdx.z * 128;

    const int ar = t >> 2, ac4 = (t & 3) * 4;
    const int br = t >> 4, bc4 = (t & 15) * 4;

    unsigned long long acc[2][4];
#pragma unroll
    for (int m = 0; m < 2; m++)
#pragma unroll
        for (int p = 0; p < 4; p++) acc[m][p] = 0ull;

    float4 av = *(const float4*)(A + (size_t)(r0 + ar) * NS + kb + ac4);
    float4 b0 = *(const float4*)(B + (size_t)(kb + br) * NS + c0 + bc4);
    float4 b1 = *(const float4*)(B + (size_t)(kb + br + 8) * NS + c0 + bc4);

    for (int it = 0; it < 8; ++it) {
        As[ac4 + 0][ar] = av.x; As[ac4 + 1][ar] = av.y;
        As[ac4 + 2][ar] = av.z; As[ac4 + 3][ar] = av.w;
        *(float4*)&Bs[br][bc4]     = b0;
        *(float4*)&Bs[br + 8][bc4] = b1;
        __syncthreads();
        if (it < 7) {
            const int k0 = kb + (it + 1) * 16;
            av = *(const float4*)(A + (size_t)(r0 + ar) * NS + k0 + ac4);
            b0 = *(const float4*)(B + (size_t)(k0 + br) * NS + c0 + bc4);
            b1 = *(const float4*)(B + (size_t)(k0 + br + 8) * NS + c0 + bc4);
        }
#pragma unroll
        for (int kk = 0; kk < 16; ++kk) {
            float a0 = As[kk][ty * 2 + 0];
            float a1 = As[kk][ty * 2 + 1];
            ulonglong2 bp0 = *(const ulonglong2*)&Bs[kk][tx * 8];
            ulonglong2 bp1 = *(const ulonglong2*)&Bs[kk][tx * 8 + 4];
            unsigned long long bv[4] = {bp0.x, bp0.y, bp1.x, bp1.y};
            unsigned long long av0, av1;
            asm("mov.b64 %0, {%1, %1};" : "=l"(av0) : "f"(a0));
            asm("mov.b64 %0, {%1, %1};" : "=l"(av1) : "f"(a1));
#pragma unroll
            for (int p = 0; p < 4; p++) {
                asm("fma.rn.f32x2 %0, %1, %2, %0;" : "+l"(acc[0][p]) : "l"(av0), "l"(bv[p]));
                asm("fma.rn.f32x2 %0, %1, %2, %0;" : "+l"(acc[1][p]) : "l"(av1), "l"(bv[p]));
            }
        }
        __syncthreads();
    }
    float* po = part + (size_t)blockIdx.z * NS2;
#pragma unroll
    for (int m = 0; m < 2; m++) {
        const int row = r0 + ty * 2 + m;
#pragma unroll
        for (int p = 0; p < 4; p++) {
            float lo, hi;
            asm("mov.b64 {%0, %1}, %2;" : "=f"(lo), "=f"(hi) : "l"(acc[m][p]));
            int col = c0 + tx * 8 + 2 * p;
            po[(size_t)row * NS + col]     = lo;
            po[(size_t)row * NS + col + 1] = hi;
        }
    }
}

__global__ void __launch_bounds__(128) k_gskz(
    float* __restrict__ Tb, float* __restrict__ part,
    int a0, int a1, int a2, int a3, int b0s, int b1s, int b2s, int b3s)
{
    const int item = blockIdx.z >> 2;
    const int ks   = blockIdx.z & 3;
    const int asl  = (item == 0) ? a0 : (item == 1) ? a1 : (item == 2) ? a2 : a3;
    const int bsl  = (item == 0) ? b0s : (item == 1) ? b1s : (item == 2) ? b2s : b3s;
    const float* A = Tb + (size_t)asl * NS2;
    const float* B = Tb + (size_t)bsl * NS2;

    __shared__ float As[16][36];
    __shared__ float Bs[16][68];
    const int t  = threadIdx.x;
    const int tx = t & 7, ty = t >> 3;
    const int r0 = blockIdx.y * 32, c0 = blockIdx.x * 64;
    const int kb = ks * 128;

    const int ar = t >> 2, ac4 = (t & 3) * 4;
    const int br = t >> 4, bc4 = (t & 15) * 4;

    unsigned long long acc[2][4];
#pragma unroll
    for (int m = 0; m < 2; m++)
#pragma unroll
        for (int p = 0; p < 4; p++) acc[m][p] = 0ull;

    float4 av = *(const float4*)(A + (size_t)(r0 + ar) * NS + kb + ac4);
    float4 b0 = *(const float4*)(B + (size_t)(kb + br) * NS + c0 + bc4);
    float4 b1 = *(const float4*)(B + (size_t)(kb + br + 8) * NS + c0 + bc4);

    for (int it = 0; it < 8; ++it) {
        As[ac4 + 0][ar] = av.x; As[ac4 + 1][ar] = av.y;
        As[ac4 + 2][ar] = av.z; As[ac4 + 3][ar] = av.w;
        *(float4*)&Bs[br][bc4]     = b0;
        *(float4*)&Bs[br + 8][bc4] = b1;
        __syncthreads();
        if (it < 7) {
            const int k0 = kb + (it + 1) * 16;
            av = *(const float4*)(A + (size_t)(r0 + ar) * NS + k0 + ac4);
            b0 = *(const float4*)(B + (size_t)(k0 + br) * NS + c0 + bc4);
            b1 = *(const float4*)(B + (size_t)(k0 + br + 8) * NS + c0 + bc4);
        }
#pragma unroll
        for (int kk = 0; kk < 16; ++kk) {
            float a0f = As[kk][ty * 2 + 0];
            float a1f = As[kk][ty * 2 + 1];
            ulonglong2 bp0 = *(const ulonglong2*)&Bs[kk][tx * 8];
            ulonglong2 bp1 = *(const ulonglong2*)&Bs[kk][tx * 8 + 4];
            unsigned long long bv[4] = {bp0.x, bp0.y, bp1.x, bp1.y};
            unsigned long long av0, av1;
            asm("mov.b64 %0, {%1, %1};" : "=l"(av0) : "f"(a0f));
            asm("mov.b64 %0, {%1, %1};" : "=l"(av1) : "f"(a1f));
#pragma unroll
            for (int p = 0; p < 4; p++) {
                asm("fma.rn.f32x2 %0, %1, %2, %0;" : "+l"(acc[0][p]) : "l"(av0), "l"(bv[p]));
                asm("fma.rn.f32x2 %0, %1, %2, %0;" : "+l"(acc[1][p]) : "l"(av1), "l"(bv[p]));
            }
        }
        __syncthreads();
    }
    float* po = part + (size_t)(item * 4 + ks) * NS2;
#pragma unroll
    for (int m = 0; m < 2; m++) {
        const int row = r0 + ty * 2 + m;
#pragma unroll
        for (int p = 0; p < 4; p++) {
            float lo, hi;
            asm("mov.b64 {%0, %1}, %2;" : "=f"(lo), "=f"(hi) : "l"(acc[m][p]));
            int col = c0 + tx * 8 + 2 * p;
            po[(size_t)row * NS + col]     = lo;
            po[(size_t)row * NS + col + 1] = hi;
        }
    }
}

__global__ void k_gred(float* __restrict__ C, const float* __restrict__ part,
                       const float* __restrict__ base) {
    int idx = blockIdx.x * 256 + threadIdx.x;
    size_t o = (size_t)idx * 4;
    float4 p0 = *(const float4*)(part + 0 * (size_t)NS2 + o);
    float4 p1 = *(const float4*)(part + 1 * (size_t)NS2 + o);
    float4 p2 = *(const float4*)(part + 2 * (size_t)NS2 + o);
    float4 p3 = *(const float4*)(part + 3 * (size_t)NS2 + o);
    float4 b = base ? *(const float4*)(base + o) : make_float4(0.f, 0.f, 0.f, 0.f);
    float4 r;
    r.x = b.x + (p0.x + p1.x) + (p2.x + p3.x);
    r.y = b.y + (p0.y + p1.y) + (p2.y + p3.y);
    r.z = b.z + (p0.z + p1.z) + (p2.z + p3.z);
    r.w = b.w + (p0.w + p1.w) + (p2.w + p3.w);
    *(float4*)(C + o) = r;
}

__global__ void k_gredz(float* __restrict__ Tb, const float* __restrict__ part,
                        int d0, int d1, int d2, int d3) {
    const int item = blockIdx.y;
    const int dsl  = (item == 0) ? d0 : (item == 1) ? d1 : (item == 2) ? d2 : d3;
    int idx = blockIdx.x * 256 + threadIdx.x;
    size_t o = (size_t)idx * 4;
    const float* p = part + (size_t)(item * 4) * NS2;
    float4 p0 = *(const float4*)(p + 0 * (size_t)NS2 + o);
    float4 p1 = *(const float4*)(p + 1 * (size_t)NS2 + o);
    float4 p2 = *(const float4*)(p + 2 * (size_t)NS2 + o);
    float4 p3 = *(const float4*)(p + 3 * (size_t)NS2 + o);
    float4 r;
    r.x = (p0.x + p1.x) + (p2.x + p3.x);
    r.y = (p0.y + p1.y) + (p2.y + p3.y);
    r.z = (p0.z + p1.z) + (p2.z + p3.z);
    r.w = (p0.w + p1.w) + (p2.w + p3.w);
    *(float4*)(Tb + (size_t)dsl * NS2 + o) = r;
}

// ---------------- vw[j] = [w,v] @ T_j (j=1..7) ----------------
__global__ void k_vw(const float* __restrict__ Tb, float* __restrict__ vw) {
    const int j = blockIdx.z + 1;
    const float* T = Tb + (size_t)j * NS2;
    const int c = blockIdx.x * 256 + threadIdx.x;

    __shared__ float v0s[5 * NS];
    for (int i = threadIdx.x; i < 5 * NS; i += 256) v0s[i] = vw[i];
    __syncthreads();

    float acc0 = 0.f, acc1 = 0.f, acc2 = 0.f, acc3 = 0.f, acc4 = 0.f;
    for (int k = 0; k < NS; ++k) {
        float tk = T[(size_t)k * NS + c];
        acc0 += v0s[0 * NS + k] * tk;
        acc1 += v0s[1 * NS + k] * tk;
        acc2 += v0s[2 * NS + k] * tk;
        acc3 += v0s[3 * NS + k] * tk;
        acc4 += v0s[4 * NS + k] * tk;
    }
    float* o = vw + (size_t)j * 5 * NS;
    o[0 * NS + c] = acc0; o[1 * NS + c] = acc1; o[2 * NS + c] = acc2;
    o[3 * NS + c] = acc3; o[4 * NS + c] = acc4;
}

// vw[8k+j] = vw[j] @ T_{8k}, k=1..7, j=0..7 (one launch, all independent)
__global__ void k_vwx(const float* __restrict__ Tb, float* __restrict__ vw) {
    const int z = blockIdx.z;             // 0..6 -> k = z+1, slot 8+z
    const float* T = Tb + (size_t)(8 + z) * NS2;
    const int vid = blockIdx.y;           // 0..39
    const int j = vid / 5, comp = vid - 5 * j;
    const float* src = vw + (size_t)(j * 5 + comp) * NS;
    float* dst = vw + (size_t)((8 * (z + 1) + j) * 5 + comp) * NS;

    __shared__ float xs[NS];
    for (int i = threadIdx.x; i < NS; i += 256) xs[i] = src[i];
    __syncthreads();
    const int c = blockIdx.x * 256 + threadIdx.x;
    float acc = 0.f;
    for (int k = 0; k < NS; ++k) acc += xs[k] * T[(size_t)k * NS + c];
    dst[c] = acc;
}

__global__ void k_cv(const float* __restrict__ vw, float* __restrict__ cv) {
    int c = blockIdx.x * 256 + threadIdx.x;
    if (c >= NS) return;
    float acc = 0.f;
    for (int j = 0; j < 64; ++j) {
        acc += vw[((size_t)j * 5 + 4) * NS + c];
        cv[(size_t)j * NS + c] = acc;
    }
}

// ---------------- E0: prefixes within 8 (non-anchors) / within 64 (rows ≡0 mod 8) ----------------
__device__ __forceinline__ float dev_interp(const float* __restrict__ Tt,
                                            const float* __restrict__ Tv, float tq) {
    if (tq <= Tt[0])      return Tv[0];
    if (tq >= Tt[ND - 1]) return Tv[ND - 1];
    int lo = 0, hi = ND - 1;
    while (hi - lo > 1) {
        int mid = (lo + hi) >> 1;
        if (Tt[mid] <= tq) lo = mid; else hi = mid;
    }
    float x0 = Tt[lo], x1 = Tt[lo + 1];
    return Tv[lo] + (tq - x0) * (Tv[lo + 1] - Tv[lo]) / (x1 - x0);
}

__global__ void k_buildE0(const float* __restrict__ Tt, const float* __restrict__ Tv,
                          const float* __restrict__ iv, const float* __restrict__ vw,
                          const float* __restrict__ cv, float* __restrict__ E0)
{
    const int g = blockIdx.x;       // rows 64g..64g+63
    const int t = threadIdx.x;      // 256
    __shared__ float s[127][4];     // d indices 64(g-1) .. 64g+62
    const int d0 = 64 * g - 64;
    for (int idx = t; idx < 508; idx += 256) {
        int jj = idx >> 2, ii = idx & 3;
        int d = d0 + jj;
        if (d >= 0) {
            float tq = (float)d * DTC + (float)ii * 10.0f;
            s[jj][ii] = dev_interp(Tt, Tv, tq);
        }
    }
    __syncthreads();

    const int i1 = t, i2 = t + 256;
#pragma unroll 1
    for (int r = 0; r < 64; ++r) {
        const int n = 64 * g + r;
        if (n >= TN) break;
        float* row = E0 + (size_t)n * NS;
        if (n == 0) {
            row[i1] = iv[i1]; row[i2] = iv[i2];
            continue;
        }
        const int rq = r & 7;
        const int p = (r == 0) ? 64 : (rq ? rq : r);
        const float* cvp = cv + (size_t)(p - 1) * NS;
        float acc1 = cvp[i1], acc2 = cvp[i2];
#pragma unroll 1
        for (int jj = 0; jj < p; ++jj) {
            const float* sj = s[64 + r - 1 - jj];
            const float* base = vw + (size_t)jj * 5 * NS;
            float s0 = sj[0], s1v = sj[1], s2v = sj[2], s3v = sj[3];
            acc1 += s0 * base[i1] + s1v * base[NS + i1]
                  + s2v * base[2 * NS + i1] + s3v * base[3 * NS + i1];
            acc2 += s0 * base[i2] + s1v * base[NS + i2]
                  + s2v * base[2 * NS + i2] + s3v * base[3 * NS + i2];
        }
        row[i1] = acc1; row[i2] = acc2;
    }
}

// ---------------- super-anchor scan, split-K partials ----------------
// part[z*SKR + s] = partial of T_{64m} · E0[64(s-m)], z = (m-1)*4 + ks
__global__ void __launch_bounds__(128, 4) k_superA(
    const float* __restrict__ V, const float* __restrict__ Tb, float* __restrict__ part)
{
    const int z  = blockIdx.z;
    const int m  = (z >> 2) + 1;          // 1..3
    const int ks = z & 3;
    const int kb = ks * 128;
    const float* W = Tb + (size_t)(14 + m) * NS2;   // T64/T128/T192

    __shared__ float As[16][132];
    __shared__ float Bs[16][68];
    const int t  = threadIdx.x;
    const int tx = t & 7, ty = t >> 3;
    const int r0 = blockIdx.y * 128;
    const int c0 = blockIdx.x * 64;

    const int ar = t >> 2, ac4 = (t & 3) * 4;
    long gr[4]; bool v[4];
#pragma unroll
    for (int g = 0; g < 4; g++) {
        int lo = r0 + ar + 32 * g;
        v[g]  = (lo < NSUP) && (lo >= m);
        gr[g] = (long)(lo - m) * 64;
    }
    const int br = t >> 4, bc4 = (t & 15) * 4;

    unsigned long long acc[8][4];
#pragma unroll
    for (int mm = 0; mm < 8; mm++)
#pragma unroll
        for (int p = 0; p < 4; p++) acc[mm][p] = 0ull;

    const float4 f4z = make_float4(0.f, 0.f, 0.f, 0.f);
    float4 av[4], b0, b1;
#pragma unroll
    for (int g = 0; g < 4; g++)
        av[g] = v[g] ? *(const float4*)(V + gr[g] * NS + kb + ac4) : f4z;
    b0 = *(const float4*)(W + (size_t)(kb + br) * NS + c0 + bc4);
    b1 = *(const float4*)(W + (size_t)(kb + br + 8) * NS + c0 + bc4);

    for (int it = 0; it < 8; ++it) {
#pragma unroll
        for (int g = 0; g < 4; g++) {
            As[ac4 + 0][ar + 32 * g] = av[g].x;
            As[ac4 + 1][ar + 32 * g] = av[g].y;
            As[ac4 + 2][ar + 32 * g] = av[g].z;
            As[ac4 + 3][ar + 32 * g] = av[g].w;
        }
        *(float4*)&Bs[br][bc4]     = b0;
        *(float4*)&Bs[br + 8][bc4] = b1;
        __syncthreads();
        if (it < 7) {
            const int k0 = kb + (it + 1) * 16;
#pragma unroll
            for (int g = 0; g < 4; g++)
                av[g] = v[g] ? *(const float4*)(V + gr[g] * NS + k0 + ac4) : f4z;
            b0 = *(const float4*)(W + (size_t)(k0 + br) * NS + c0 + bc4);
            b1 = *(const float4*)(W + (size_t)(k0 + br + 8) * NS + c0 + bc4);
        }
#pragma unroll
        for (int kk = 0; kk < 16; ++kk) {
            float a[8];
            *(float4*)&a[0] = *(const float4*)&As[kk][ty * 8];
            *(float4*)&a[4] = *(const float4*)&As[kk][ty * 8 + 4];
            ulonglong2 bp0 = *(const ulonglong2*)&Bs[kk][tx * 8];
            ulonglong2 bp1 = *(const ulonglong2*)&Bs[kk][tx * 8 + 4];
            unsigned long long bv[4] = {bp0.x, bp0.y, bp1.x, bp1.y};
#pragma unroll
            for (int mm = 0; mm < 8; mm++) {
                unsigned long long avv;
                asm("mov.b64 %0, {%1, %1};" : "=l"(avv) : "f"(a[mm]));
#pragma unroll
                for (int p = 0; p < 4; p++)
                    asm("fma.rn.f32x2 %0, %1, %2, %0;"
                        : "+l"(acc[mm][p]) : "l"(avv), "l"(bv[p]));
            }
        }
        __syncthreads();
    }
#pragma unroll
    for (int mm = 0; mm < 8; mm++) {
        const int r = r0 + ty * 8 + mm;
        if (r < NSUP) {
            float c[8];
#pragma unroll
            for (int p = 0; p < 4; p++)
                asm("mov.b64 {%0, %1}, %2;"
                    : "=f"(c[2 * p]), "=f"(c[2 * p + 1]) : "l"(acc[mm][p]));
            float* prow = part + ((size_t)z * SKR + r) * NS + c0 + tx * 8;
            *(float4*)prow       = make_float4(c[0], c[1], c[2], c[3]);
            *(float4*)(prow + 4) = make_float4(c[4], c[5], c[6], c[7]);
        }
    }
}

// V[64s] += sum of 12 partials (fixed order)
__global__ void k_superB(float* __restrict__ V, const float* __restrict__ part) {
    int idx = blockIdx.x * 256 + threadIdx.x;
    if (idx >= NSUP * 128) return;
    int r  = idx >> 7;
    int c4 = (idx & 127) << 2;
    float4 sum = make_float4(0.f, 0.f, 0.f, 0.f);
#pragma unroll
    for (int z = 0; z < 12; ++z) {
        float4 p = *(const float4*)(part + ((size_t)z * SKR + r) * NS + c4);
        sum.x += p.x; sum.y += p.y; sum.z += p.z; sum.w += p.w;
    }
    float* dst = V + (size_t)r * 64 * NS + c4;
    float4 d = *(const float4*)dst;
    d.x += sum.x; d.y += sum.y; d.z += sum.z; d.w += sum.w;
    *(float4*)dst = d;
}

// ---------------- anchor fill, split-K partials: T_{8k} · x[64s], z=(k-1)*4+ks ----------------
__global__ void __launch_bounds__(128, 4) k_afill(
    const float* __restrict__ V, const float* __restrict__ Tb, float* __restrict__ part)
{
    const int z  = blockIdx.z;
    const int k  = (z >> 2) + 1;          // 1..7
    const int ks = z & 3;
    const int kb = ks * 128;
    const float* W = Tb + (size_t)(7 + k) * NS2;    // T8..T56

    __shared__ float As[16][132];
    __shared__ float Bs[16][68];
    const int t  = threadIdx.x;
    const int tx = t & 7, ty = t >> 3;
    const int r0 = blockIdx.y * 128;
    const int c0 = blockIdx.x * 64;

    const int ar = t >> 2, ac4 = (t & 3) * 4;
    long gr[4]; bool v[4];
#pragma unroll
    for (int g = 0; g < 4; g++) {
        int lo = r0 + ar + 32 * g;
        v[g]  = lo < NSUP;
        gr[g] = (long)lo * 64;
    }
    const int br = t >> 4, bc4 = (t & 15) * 4;

    unsigned long long acc[8][4];
#pragma unroll
    for (int mm = 0; mm < 8; mm++)
#pragma unroll
        for (int p = 0; p < 4; p++) acc[mm][p] = 0ull;

    const float4 f4z = make_float4(0.f, 0.f, 0.f, 0.f);
    float4 av[4], b0, b1;
#pragma unroll
    for (int g = 0; g < 4; g++)
        av[g] = v[g] ? *(const float4*)(V + gr[g] * NS + kb + ac4) : f4z;
    b0 = *(const float4*)(W + (size_t)(kb + br) * NS + c0 + bc4);
    b1 = *(const float4*)(W + (size_t)(kb + br + 8) * NS + c0 + bc4);

    for (int it = 0; it < 8; ++it) {
#pragma unroll
        for (int g = 0; g < 4; g++) {
            As[ac4 + 0][ar + 32 * g] = av[g].x;
            As[ac4 + 1][ar + 32 * g] = av[g].y;
            As[ac4 + 2][ar + 32 * g] = av[g].z;
            As[ac4 + 3][ar + 32 * g] = av[g].w;
        }
        *(float4*)&Bs[br][bc4]     = b0;
        *(float4*)&Bs[br + 8][bc4] = b1;
        __syncthreads();
        if (it < 7) {
            const int k0 = kb + (it + 1) * 16;
#pragma unroll
            for (int g = 0; g < 4; g++)
                av[g] = v[g] ? *(const float4*)(V + gr[g] * NS + k0 + ac4) : f4z;
            b0 = *(const float4*)(W + (size_t)(k0 + br) * NS + c0 + bc4);
            b1 = *(const float4*)(W + (size_t)(k0 + br + 8) * NS + c0 + bc4);
        }
#pragma unroll
        for (int kk = 0; kk < 16; ++kk) {
            float a[8];
            *(float4*)&a[0] = *(const float4*)&As[kk][ty * 8];
            *(float4*)&a[4] = *(const float4*)&As[kk][ty * 8 + 4];
            ulonglong2 bp0 = *(const ulonglong2*)&Bs[kk][tx * 8];
            ulonglong2 bp1 = *(const ulonglong2*)&Bs[kk][tx * 8 + 4];
            unsigned long long bv[4] = {bp0.x, bp0.y, bp1.x, bp1.y};
#pragma unroll
            for (int mm = 0; mm < 8; mm++) {
                unsigned long long avv;
                asm("mov.b64 %0, {%1, %1};" : "=l"(avv) : "f"(a[mm]));
#pragma unroll
                for (int p = 0; p < 4; p++)
                    asm("fma.rn.f32x2 %0, %1, %2, %0;"
                        : "+l"(acc[mm][p]) : "l"(avv), "l"(bv[p]));
            }
        }
        __syncthreads();
    }
#pragma unroll
    for (int mm = 0; mm < 8; mm++) {
        const int r = r0 + ty * 8 + mm;
        if (r < NSUP) {
            float c[8];
#pragma unroll
            for (int p = 0; p < 4; p++)
                asm("mov.b64 {%0, %1}, %2;"
                    : "=f"(c[2 * p]), "=f"(c[2 * p + 1]) : "l"(acc[mm][p]));
            float* prow = part + ((size_t)z * SKR + r) * NS + c0 + tx * 8;
            *(float4*)prow       = make_float4(c[0], c[1], c[2], c[3]);
            *(float4*)(prow + 4) = make_float4(c[4], c[5], c[6], c[7]);
        }
    }
}

// V[64s+8k] += 4 partials of T_{8k} x[64s]
__global__ void k_afill_red(float* __restrict__ V, const float* __restrict__ part) {
    int idx = blockIdx.x * 256 + threadIdx.x;
    const int per_k = NSUP * 128;
    if (idx >= 7 * per_k) return;
    int kk = idx / per_k;
    int rem = idx - kk * per_k;
    int r  = rem >> 7;
    int c4 = (rem & 127) << 2;
    long dr = (long)r * 64 + 8 * (kk + 1);
    if (dr >= TN) return;
    float4 p0 = *(const float4*)(part + (((size_t)(kk * 4 + 0)) * SKR + r) * NS + c4);
    float4 p1 = *(const float4*)(part + (((size_t)(kk * 4 + 1)) * SKR + r) * NS + c4);
    float4 p2 = *(const float4*)(part + (((size_t)(kk * 4 + 2)) * SKR + r) * NS + c4);
    float4 p3 = *(const float4*)(part + (((size_t)(kk * 4 + 3)) * SKR + r) * NS + c4);
    float* dst = V + dr * NS + c4;
    float4 d = *(const float4*)dst;
    d.x += (p0.x + p1.x) + (p2.x + p3.x);
    d.y += (p0.y + p1.y) + (p2.y + p3.y);
    d.z += (p0.z + p1.z) + (p2.z + p3.z);
    d.w += (p0.w + p1.w) + (p2.w + p3.w);
    *(float4*)dst = d;
}

// ---------------- flat fill (verbatim R12): x[8r+q] = E[8r+q] + T_q x[8r] ----------------
__global__ void __launch_bounds__(128, 4) k_fillz(
    float* __restrict__ V, const float* __restrict__ Tb, int cnt)
{
    const int q = blockIdx.z + 1;
    const float* W = Tb + (size_t)q * NS2;

    __shared__ float As[16][132];
    __shared__ float Bs[16][68];

    const int t  = threadIdx.x;
    const int tx = t & 7;
    const int ty = t >> 3;
    const int r0 = blockIdx.y * 128;
    const int c0 = blockIdx.x * 64;

    const int  ar  = t >> 2;
    const int  ac4 = (t & 3) * 4;
    long gr[4]; bool v[4];
#pragma unroll
    for (int g = 0; g < 4; g++) {
        int lo = r0 + ar + 32 * g;
        v[g]  = lo < cnt;
        gr[g] = (long)lo * RAD;
    }

    const int br  = t >> 4;
    const int bc4 = (t & 15) * 4;

    unsigned long long acc[8][4];
#pragma unroll
    for (int m = 0; m < 8; m++)
#pragma unroll
        for (int p = 0; p < 4; p++) acc[m][p] = 0ull;

    const float4 f4z = make_float4(0.f, 0.f, 0.f, 0.f);
    float4 av[4], b0, b1;
#pragma unroll
    for (int g = 0; g < 4; g++)
        av[g] = v[g] ? *(const float4*)(V + gr[g] * NS + ac4) : f4z;
    b0 = *(const float4*)(W + (size_t)br * NS + c0 + bc4);
    b1 = *(const float4*)(W + (size_t)(br + 8) * NS + c0 + bc4);

    for (int it = 0; it < 32; ++it) {
#pragma unroll
        for (int g = 0; g < 4; g++) {
            As[ac4 + 0][ar + 32 * g] = av[g].x;
            As[ac4 + 1][ar + 32 * g] = av[g].y;
            As[ac4 + 2][ar + 32 * g] = av[g].z;
            As[ac4 + 3][ar + 32 * g] = av[g].w;
        }
        *(float4*)&Bs[br][bc4]     = b0;
        *(float4*)&Bs[br + 8][bc4] = b1;
        __syncthreads();

        if (it < 31) {
            const int k0 = (it + 1) * 16;
#pragma unroll
            for (int g = 0; g < 4; g++)
                av[g] = v[g] ? *(const float4*)(V + gr[g] * NS + k0 + ac4) : f4z;
            b0 = *(const float4*)(W + (size_t)(k0 + br) * NS + c0 + bc4);
            b1 = *(const float4*)(W + (size_t)(k0 + br + 8) * NS + c0 + bc4);
        }

#pragma unroll
        for (int kk = 0; kk < 16; ++kk) {
            float a[8];
            *(float4*)&a[0] = *(const float4*)&As[kk][ty * 8];
            *(float4*)&a[4] = *(const float4*)&As[kk][ty * 8 + 4];
            ulonglong2 bp0 = *(const ulonglong2*)&Bs[kk][tx * 8];
            ulonglong2 bp1 = *(const ulonglong2*)&Bs[kk][tx * 8 + 4];
            unsigned long long bv[4] = {bp0.x, bp0.y, bp1.x, bp1.y};
#pragma unroll
            for (int m = 0; m < 8; m++) {
                unsigned long long avv;
                asm("mov.b64 %0, {%1, %1};" : "=l"(avv) : "f"(a[m]));
#pragma unroll
                for (int p = 0; p < 4; p++)
                    asm("fma.rn.f32x2 %0, %1, %2, %0;"
                        : "+l"(acc[m][p]) : "l"(avv), "l"(bv[p]));
            }
        }
        __syncthreads();
    }

#pragma unroll
    for (int m = 0; m < 8; m++) {
        const int r = r0 + ty * 8 + m;
        if (r < cnt) {
            const long dr = (long)r * RAD + q;
            float* erow = V + dr * NS + c0 + tx * 8;
            float4 e0 = *(const float4*)erow;
            float4 e1 = *(const float4*)(erow + 4);
            float c[8];
#pragma unroll
            for (int p = 0; p < 4; p++)
                asm("mov.b64 {%0, %1}, %2;"
                    : "=f"(c[2 * p]), "=f"(c[2 * p + 1]) : "l"(acc[m][p]));
            float4 o0 = make_float4(c[0] + e0.x, c[1] + e0.y, c[2] + e0.z, c[3] + e0.w);
            float4 o1 = make_float4(c[4] + e1.x, c[5] + e1.y, c[6] + e1.z, c[7] + e1.w);
            *(float4*)erow       = o0;
            *(float4*)(erow + 4) = o1;
        }
    }
}

// ---------------- host orchestration (graph-capturable, alloc-free) ----------------
extern "C" void kernel_launch(void* const* d_in, const int* in_sizes, int n_in,
                              void* d_out, int out_size) {
    const float* A  = (const float*)d_in[0];
    const float* Bm = (const float*)d_in[1];
    const float* Q  = (const float*)d_in[2];
    const float* Tt = (const float*)d_in[3];
    const float* Tv = (const float*)d_in[4];
    const float* iv = (const float*)d_in[5];
    float* out = (float*)d_out;

    float *Lt, *G1, *G2, *Tb, *vec, *vw, *cv, *part;
    cudaGetSymbolAddress((void**)&Lt,   d_Lt);
    cudaGetSymbolAddress((void**)&G1,   d_G1);
    cudaGetSymbolAddress((void**)&G2,   d_G2);
    cudaGetSymbolAddress((void**)&Tb,   d_T);
    cudaGetSymbolAddress((void**)&vec,  d_vec);
    cudaGetSymbolAddress((void**)&vw,   d_vw);
    cudaGetSymbolAddress((void**)&cv,   d_cv);
    cudaGetSymbolAddress((void**)&part, d_part);

    // Lt = (dt*A)^T
    k_tpose<<<1024, 256>>>(A, Lt);

    // forcing vectors w1..w4, v (into vw[0])
    k_gh<<<2, 256>>>(Bm, Q, vec + 0 * NS, vec + 1 * NS);
    k_matvec2<<<512, 128>>>(A, vec + 0 * NS, vec + 1 * NS, vec + 2 * NS, vec + 5 * NS, DTC);
    k_matvec2<<<512, 128>>>(A, vec + 2 * NS, vec + 5 * NS, vec + 3 * NS, vec + 6 * NS, DTC);
    k_matvec2<<<512, 128>>>(A, vec + 3 * NS, vec + 6 * NS, vec + 4 * NS, vec + 7 * NS, DTC);
    k_combine<<<2, 256>>>(vec, vw);

    const dim3 gsk(8, 16, 4);
    const int RB = NS2 / 4 / 256;

    // G1 = Lt^2 ; T1 = (I + Lt + G1/2) + G1 @ (Lt/6 + G1/24)
    k_gsk<<<gsk, 128>>>(Lt, Lt, part);
    k_gred<<<RB, 256>>>(G1, part, nullptr);
    k_prep1<<<1024, 256>>>(Lt, G1, G2, Tb + 0 * (size_t)NS2);
    k_gsk<<<gsk, 128>>>(G1, G2, part);
    k_gred<<<RB, 256>>>(Tb + 1 * (size_t)NS2, part, Tb + 0 * (size_t)NS2);

    // T2 ; {T3,T4} ; {T5..T8}
    k_gsk<<<gsk, 128>>>(Tb + 1 * (size_t)NS2, Tb + 1 * (size_t)NS2, part);
    k_gred<<<RB, 256>>>(Tb + 2 * (size_t)NS2, part, nullptr);
    k_gskz<<<dim3(8, 16, 8), 128>>>(Tb, part, 1, 2, 0, 0, 2, 2, 0, 0);
    k_gredz<<<dim3(RB, 2), 256>>>(Tb, part, 3, 4, 0, 0);
    k_gskz<<<dim3(8, 16, 16), 128>>>(Tb, part, 1, 2, 3, 4, 4, 4, 4, 4);
    k_gredz<<<dim3(RB, 4), 256>>>(Tb, part, 5, 6, 7, 8);

    // vw[1..7] (needs T1..T7)
    k_vw<<<dim3(2, 1, 7), 256>>>(Tb, vw);

    // T16(9) ; {T24(10), T32(11)} ; {T40(12), T48(13), T56(14), T64(15)}
    k_gsk<<<gsk, 128>>>(Tb + 8 * (size_t)NS2, Tb + 8 * (size_t)NS2, part);
    k_gred<<<RB, 256>>>(Tb + 9 * (size_t)NS2, part, nullptr);
    k_gskz<<<dim3(8, 16, 8), 128>>>(Tb, part, 8, 9, 0, 0, 9, 9, 0, 0);
    k_gredz<<<dim3(RB, 2), 256>>>(Tb, part, 10, 11, 0, 0);
    k_gskz<<<dim3(8, 16, 16), 128>>>(Tb, part, 8, 9, 10, 11, 11, 11, 11, 11);
    k_gredz<<<dim3(RB, 4), 256>>>(Tb, part, 12, 13, 14, 15);

    // vw[8..63] = vw[0..7] @ T_{8k}  (needs T8..T56) ; cv cumsums
    k_vwx<<<dim3(2, 40, 7), 256>>>(Tb, vw);
    k_cv<<<2, 256>>>(vw, cv);

    // T128(16) = T64^2 ; T192(17) = T64 @ T128
    k_gsk<<<gsk, 128>>>(Tb + 15 * (size_t)NS2, Tb + 15 * (size_t)NS2, part);
    k_gred<<<RB, 256>>>(Tb + 16 * (size_t)NS2, part, nullptr);
    k_gsk<<<gsk, 128>>>(Tb + 15 * (size_t)NS2, Tb + 16 * (size_t)NS2, part);
    k_gred<<<RB, 256>>>(Tb + 17 * (size_t)NS2, part, nullptr);

    // E0 (prefix-8 rows; prefix-64 on rows ≡ 0 mod 8)
    k_buildE0<<<NSUP, 256>>>(Tt, Tv, iv, vw, cv, out);

    // super-anchor scan: x[64s] = E0[64s] + Σ_{m=1..3} T_{64m}·E0[64(s-m)]
    k_superA<<<dim3(8, 3, 12), 128>>>(out, Tb, part);
    k_superB<<<(NSUP * 128 + 255) / 256, 256>>>(out, part);

    // anchor fill: x[64s+8k] = E0 + T_{8k}·x[64s]
    k_afill<<<dim3(8, 3, 28), 128>>>(out, Tb, part);
    k_afill_red<<<(7 * NSUP * 128 + 255) / 256, 256>>>(out, part);

    // flat fill: all non-anchor rows
    k_fillz<<<dim3(8, (NANCH + 127) / 128, RAD - 1), 128>>>(out, Tb, NANCH);
    // result in `out`
}

// round 15
// speedup vs baseline: 1.1948x; 1.0056x over previous
#include <cuda_runtime.h>

#define NS   512
#define NS2  (NS * NS)
#define TN   20000
#define ND   2000
#define DTC  30.0f
#define RAD  8          // fill radix (anchors every 8 rows)
#define NANCH 2500      // TN / RAD
#define SKROWS 1280     // split-K partial rows for anchor BK (max cnt = 1250)

// ---------------- static scratch (no allocations allowed) ----------------
__device__ float d_Lt[NS2];               // (dt*A)^T
__device__ float d_G1[NS2];               // Lt^2
__device__ float d_G2[NS2];               // H = Lt/6 + Lt^2/24
// T slots: 0 = Horner base ; 1..8 = (M^q)^T ; 9=T16,10=T32,11=T64,12=T128
__device__ float d_T[13][NS2];
__device__ float d_vec[8 * NS];
__device__ float d_vw[RAD * 5 * NS];      // vw[j] = M^j [w1..w4, v]
__device__ float d_cv[RAD * NS];          // cv[p-1] = sum_{j<p} M^j v
__device__ float d_part[16 * NS2];        // split-K partials (16.8 MB, reused)
__device__ int   d_ctr[32 * 128];         // per-tile arrival counters (memset per launch)

// ---------------- small helpers ----------------
__global__ void k_tpose(const float* __restrict__ A, float* __restrict__ Lt) {
    int idx = blockIdx.x * blockDim.x + threadIdx.x;
    if (idx < NS2) {
        int i = idx >> 9, j = idx & 511;
        Lt[idx] = DTC * A[j * NS + i];
    }
}

__global__ void k_gh(const float* __restrict__ B, const float* __restrict__ Q,
                     float* __restrict__ g, float* __restrict__ h) {
    int i = blockIdx.x * blockDim.x + threadIdx.x;
    if (i < NS) {
        g[i] = B[i * 9];
        float s = 0.f;
#pragma unroll
        for (int m = 0; m < 8; m++) s += B[i * 9 + 1 + m] * Q[m];
        h[i] = s;
    }
}

__global__ void k_matvec2(const float* __restrict__ A,
                          const float* __restrict__ x1, const float* __restrict__ x2,
                          float* __restrict__ y1, float* __restrict__ y2, float scale) {
    __shared__ float red1[128], red2[128];
    int row = blockIdx.x;
    float s1 = 0.f, s2 = 0.f;
    for (int j = threadIdx.x; j < NS; j += 128) {
        float a = A[row * NS + j];
        s1 += a * x1[j];
        s2 += a * x2[j];
    }
    red1[threadIdx.x] = s1; red2[threadIdx.x] = s2;
    __syncthreads();
    for (int st = 64; st > 0; st >>= 1) {
        if (threadIdx.x < st) {
            red1[threadIdx.x] += red1[threadIdx.x + st];
            red2[threadIdx.x] += red2[threadIdx.x + st];
        }
        __syncthreads();
    }
    if (threadIdx.x == 0) { y1[row] = scale * red1[0]; y2[row] = scale * red2[0]; }
}

__global__ void k_combine(const float* __restrict__ vec, float* __restrict__ vw) {
    int i = blockIdx.x * blockDim.x + threadIdx.x;
    if (i >= NS) return;
    const float G   = vec[0 * NS + i], H   = vec[1 * NS + i];
    const float LG  = vec[2 * NS + i], L2G = vec[3 * NS + i], L3G = vec[4 * NS + i];
    const float LH  = vec[5 * NS + i], L2H = vec[6 * NS + i], L3H = vec[7 * NS + i];
    const float c = DTC / 8.0f;
    vw[0 * NS + i] = c * (G + LG + (L2G + L3G) * (1.0f / 3.0f));
    vw[1 * NS + i] = c * (3.0f * G + 2.0f * LG + L2G);
    vw[2 * NS + i] = c * (3.0f * G + LG);
    vw[3 * NS + i] = c * G;
    vw[4 * NS + i] = DTC * (H + 0.5f * LH + L2H * (1.0f / 6.0f) + L3H * (1.0f / 24.0f));
}

__global__ void k_prep1(const float* __restrict__ Lt, const float* __restrict__ G1,
                        float* __restrict__ H, float* __restrict__ base) {
    int idx = blockIdx.x * blockDim.x + threadIdx.x;
    if (idx < NS2) {
        int i = idx >> 9, j = idx & 511;
        float l = Lt[idx], g = G1[idx];
        H[idx]    = l * (1.0f / 6.0f) + g * (1.0f / 24.0f);
        base[idx] = l + 0.5f * g + (i == j ? 1.0f : 0.0f);
    }
}

// ---------------- fused split-K 512^3 GEMM: partials + last-block reduce ----------------
// C[tile] = (base?) + p0+p1 + p2+p3   (fixed order, done once per tile)
__global__ void __launch_bounds__(128) k_gsk(
    const float* __restrict__ A, const float* __restrict__ B, float* __restrict__ part,
    float* __restrict__ C, const float* __restrict__ base, int* __restrict__ ctr)
{
    __shared__ float As[16][36];
    __shared__ float Bs[16][68];
    __shared__ int s_old;
    const int t  = threadIdx.x;
    const int tx = t & 7, ty = t >> 3;
    const int r0 = blockIdx.y * 32, c0 = blockIdx.x * 64;
    const int kb = blockIdx.z * 128;

    const int ar = t >> 2, ac4 = (t & 3) * 4;
    const int br = t >> 4, bc4 = (t & 15) * 4;

    unsigned long long acc[2][4];
#pragma unroll
    for (int m = 0; m < 2; m++)
#pragma unroll
        for (int p = 0; p < 4; p++) acc[m][p] = 0ull;

    float4 av = *(const float4*)(A + (size_t)(r0 + ar) * NS + kb + ac4);
    float4 b0 = *(const float4*)(B + (size_t)(kb + br) * NS + c0 + bc4);
    float4 b1 = *(const float4*)(B + (size_t)(kb + br + 8) * NS + c0 + bc4);

    for (int it = 0; it < 8; ++it) {
        As[ac4 + 0][ar] = av.x; As[ac4 + 1][ar] = av.y;
        As[ac4 + 2][ar] = av.z; As[ac4 + 3][ar] = av.w;
        *(float4*)&Bs[br][bc4]     = b0;
        *(float4*)&Bs[br + 8][bc4] = b1;
        __syncthreads();
        if (it < 7) {
            const int k0 = kb + (it + 1) * 16;
            av = *(const float4*)(A + (size_t)(r0 + ar) * NS + k0 + ac4);
            b0 = *(const float4*)(B + (size_t)(k0 + br) * NS + c0 + bc4);
            b1 = *(const float4*)(B + (size_t)(k0 + br + 8) * NS + c0 + bc4);
        }
#pragma unroll
        for (int kk = 0; kk < 16; ++kk) {
            float a0 = As[kk][ty * 2 + 0];
            float a1 = As[kk][ty * 2 + 1];
            ulonglong2 bp0 = *(const ulonglong2*)&Bs[kk][tx * 8];
            ulonglong2 bp1 = *(const ulonglong2*)&Bs[kk][tx * 8 + 4];
            unsigned long long bv[4] = {bp0.x, bp0.y, bp1.x, bp1.y};
            unsigned long long av0, av1;
            asm("mov.b64 %0, {%1, %1};" : "=l"(av0) : "f"(a0));
            asm("mov.b64 %0, {%1, %1};" : "=l"(av1) : "f"(a1));
#pragma unroll
            for (int p = 0; p < 4; p++) {
                asm("fma.rn.f32x2 %0, %1, %2, %0;" : "+l"(acc[0][p]) : "l"(av0), "l"(bv[p]));
                asm("fma.rn.f32x2 %0, %1, %2, %0;" : "+l"(acc[1][p]) : "l"(av1), "l"(bv[p]));
            }
        }
        __syncthreads();
    }
    float* po = part + (size_t)blockIdx.z * NS2;
#pragma unroll
    for (int m = 0; m < 2; m++) {
        const int row = r0 + ty * 2 + m;
#pragma unroll
        for (int p = 0; p < 4; p++) {
            float lo, hi;
            asm("mov.b64 {%0, %1}, %2;" : "=f"(lo), "=f"(hi) : "l"(acc[m][p]));
            int col = c0 + tx * 8 + 2 * p;
            po[(size_t)row * NS + col]     = lo;
            po[(size_t)row * NS + col + 1] = hi;
        }
    }

    // last block of the 4 k-splits reduces this tile
    __threadfence();
    __syncthreads();
    if (t == 0) s_old = atomicAdd(&ctr[blockIdx.y * 8 + blockIdx.x], 1);
    __syncthreads();
    if (s_old == 3) {
        __threadfence();
        for (int i = t; i < 512; i += 128) {          // 32 rows x 16 float4
            int row = r0 + (i >> 4);
            size_t o = (size_t)row * NS + c0 + ((i & 15) << 2);
            float4 p0 = *(const float4*)(part + 0 * (size_t)NS2 + o);
            float4 p1 = *(const float4*)(part + 1 * (size_t)NS2 + o);
            float4 p2 = *(const float4*)(part + 2 * (size_t)NS2 + o);
            float4 p3 = *(const float4*)(part + 3 * (size_t)NS2 + o);
            float4 b = base ? *(const float4*)(base + o) : make_float4(0.f, 0.f, 0.f, 0.f);
            float4 r;
            r.x = b.x + (p0.x + p1.x) + (p2.x + p3.x);
            r.y = b.y + (p0.y + p1.y) + (p2.y + p3.y);
            r.z = b.z + (p0.z + p1.z) + (p2.z + p3.z);
            r.w = b.w + (p0.w + p1.w) + (p2.w + p3.w);
            *(float4*)(C + o) = r;
        }
    }
}

// batched fused split-K over T slots: item = z>>2, ksplit = z&3
__global__ void __launch_bounds__(128) k_gskz(
    float* __restrict__ Tb, float* __restrict__ part, int* __restrict__ ctr,
    int a0, int a1, int a2, int a3, int b0s, int b1s, int b2s, int b3s,
    int d0, int d1, int d2, int d3)
{
    const int item = blockIdx.z >> 2;
    const int ks   = blockIdx.z & 3;
    const int asl  = (item == 0) ? a0 : (item == 1) ? a1 : (item == 2) ? a2 : a3;
    const int bsl  = (item == 0) ? b0s : (item == 1) ? b1s : (item == 2) ? b2s : b3s;
    const int dsl  = (item == 0) ? d0 : (item == 1) ? d1 : (item == 2) ? d2 : d3;
    const float* A = Tb + (size_t)asl * NS2;
    const float* B = Tb + (size_t)bsl * NS2;

    __shared__ float As[16][36];
    __shared__ float Bs[16][68];
    __shared__ int s_old;
    const int t  = threadIdx.x;
    const int tx = t & 7, ty = t >> 3;
    const int r0 = blockIdx.y * 32, c0 = blockIdx.x * 64;
    const int kb = ks * 128;

    const int ar = t >> 2, ac4 = (t & 3) * 4;
    const int br = t >> 4, bc4 = (t & 15) * 4;

    unsigned long long acc[2][4];
#pragma unroll
    for (int m = 0; m < 2; m++)
#pragma unroll
        for (int p = 0; p < 4; p++) acc[m][p] = 0ull;

    float4 av = *(const float4*)(A + (size_t)(r0 + ar) * NS + kb + ac4);
    float4 b0 = *(const float4*)(B + (size_t)(kb + br) * NS + c0 + bc4);
    float4 b1 = *(const float4*)(B + (size_t)(kb + br + 8) * NS + c0 + bc4);

    for (int it = 0; it < 8; ++it) {
        As[ac4 + 0][ar] = av.x; As[ac4 + 1][ar] = av.y;
        As[ac4 + 2][ar] = av.z; As[ac4 + 3][ar] = av.w;
        *(float4*)&Bs[br][bc4]     = b0;
        *(float4*)&Bs[br + 8][bc4] = b1;
        __syncthreads();
        if (it < 7) {
            const int k0 = kb + (it + 1) * 16;
            av = *(const float4*)(A + (size_t)(r0 + ar) * NS + k0 + ac4);
            b0 = *(const float4*)(B + (size_t)(k0 + br) * NS + c0 + bc4);
            b1 = *(const float4*)(B + (size_t)(k0 + br + 8) * NS + c0 + bc4);
        }
#pragma unroll
        for (int kk = 0; kk < 16; ++kk) {
            float a0f = As[kk][ty * 2 + 0];
            float a1f = As[kk][ty * 2 + 1];
            ulonglong2 bp0 = *(const ulonglong2*)&Bs[kk][tx * 8];
            ulonglong2 bp1 = *(const ulonglong2*)&Bs[kk][tx * 8 + 4];
            unsigned long long bv[4] = {bp0.x, bp0.y, bp1.x, bp1.y};
            unsigned long long av0, av1;
            asm("mov.b64 %0, {%1, %1};" : "=l"(av0) : "f"(a0f));
            asm("mov.b64 %0, {%1, %1};" : "=l"(av1) : "f"(a1f));
#pragma unroll
            for (int p = 0; p < 4; p++) {
                asm("fma.rn.f32x2 %0, %1, %2, %0;" : "+l"(acc[0][p]) : "l"(av0), "l"(bv[p]));
                asm("fma.rn.f32x2 %0, %1, %2, %0;" : "+l"(acc[1][p]) : "l"(av1), "l"(bv[p]));
            }
        }
        __syncthreads();
    }
    float* po = part + (size_t)(item * 4 + ks) * NS2;
#pragma unroll
    for (int m = 0; m < 2; m++) {
        const int row = r0 + ty * 2 + m;
#pragma unroll
        for (int p = 0; p < 4; p++) {
            float lo, hi;
            asm("mov.b64 {%0, %1}, %2;" : "=f"(lo), "=f"(hi) : "l"(acc[m][p]));
            int col = c0 + tx * 8 + 2 * p;
            po[(size_t)row * NS + col]     = lo;
            po[(size_t)row * NS + col + 1] = hi;
        }
    }

    __threadfence();
    __syncthreads();
    if (t == 0) s_old = atomicAdd(&ctr[item * 128 + blockIdx.y * 8 + blockIdx.x], 1);
    __syncthreads();
    if (s_old == 3) {
        __threadfence();
        const float* p = part + (size_t)(item * 4) * NS2;
        float* Cd = Tb + (size_t)dsl * NS2;
        for (int i = t; i < 512; i += 128) {
            int row = r0 + (i >> 4);
            size_t o = (size_t)row * NS + c0 + ((i & 15) << 2);
            float4 p0 = *(const float4*)(p + 0 * (size_t)NS2 + o);
            float4 p1 = *(const float4*)(p + 1 * (size_t)NS2 + o);
            float4 p2 = *(const float4*)(p + 2 * (size_t)NS2 + o);
            float4 p3 = *(const float4*)(p + 3 * (size_t)NS2 + o);
            float4 r;
            r.x = (p0.x + p1.x) + (p2.x + p3.x);
            r.y = (p0.y + p1.y) + (p2.y + p3.y);
            r.z = (p0.z + p1.z) + (p2.z + p3.z);
            r.w = (p0.w + p1.w) + (p2.w + p3.w);
            *(float4*)(Cd + o) = r;
        }
    }
}

// ---------------- vw[j] = [w1..w4,v] @ T_j (j=1..7, batched) ----------------
__global__ void k_vw(const float* __restrict__ Tb, float* __restrict__ vw) {
    const int j = blockIdx.z + 1;
    const float* T = Tb + (size_t)j * NS2;
    const int c = blockIdx.x * 256 + threadIdx.x;

    __shared__ float v0s[5 * NS];
    for (int i = threadIdx.x; i < 5 * NS; i += 256) v0s[i] = vw[i];
    __syncthreads();

    float acc0 = 0.f, acc1 = 0.f, acc2 = 0.f, acc3 = 0.f, acc4 = 0.f;
    for (int k = 0; k < NS; ++k) {
        float tk = T[(size_t)k * NS + c];
        acc0 += v0s[0 * NS + k] * tk;
        acc1 += v0s[1 * NS + k] * tk;
        acc2 += v0s[2 * NS + k] * tk;
        acc3 += v0s[3 * NS + k] * tk;
        acc4 += v0s[4 * NS + k] * tk;
    }
    float* o = vw + (size_t)j * 5 * NS;
    o[0 * NS + c] = acc0; o[1 * NS + c] = acc1; o[2 * NS + c] = acc2;
    o[3 * NS + c] = acc3; o[4 * NS + c] = acc4;
}

__global__ void k_cv(const float* __restrict__ vw, float* __restrict__ cv) {
    int c = blockIdx.x * 256 + threadIdx.x;
    if (c >= NS) return;
    float acc = 0.f;
    for (int j = 0; j < RAD; ++j) {
        acc += vw[((size_t)j * 5 + 4) * NS + c];
        cv[(size_t)j * NS + c] = acc;
    }
}

// ---------------- grouped E0: one block per group of 8 rows ----------------
__device__ __forceinline__ float dev_interp(const float* __restrict__ Tt,
                                            const float* __restrict__ Tv, float tq) {
    if (tq <= Tt[0])      return Tv[0];
    if (tq >= Tt[ND - 1]) return Tv[ND - 1];
    int lo = 0, hi = ND - 1;
    while (hi - lo > 1) {
        int mid = (lo + hi) >> 1;
        if (Tt[mid] <= tq) lo = mid; else hi = mid;
    }
    float x0 = Tt[lo], x1 = Tt[lo + 1];
    return Tv[lo] + (tq - x0) * (Tv[lo + 1] - Tv[lo]) / (x1 - x0);
}

__global__ void k_buildE0(const float* __restrict__ Tt, const float* __restrict__ Tv,
                          const float* __restrict__ iv, const float* __restrict__ vw,
                          const float* __restrict__ cv, float* __restrict__ E0)
{
    const int g = blockIdx.x;       // rows 8g..8g+7
    const int t = threadIdx.x;      // 256
    __shared__ float s[15][4];      // d indices 8g-8 .. 8g+6
    const int d0 = 8 * g - 8;
    if (t < 60) {
        int jj = t >> 2, ii = t & 3;
        int d = d0 + jj;
        if (d >= 0) {
            float tq = (float)d * DTC + (float)ii * 10.0f;
            s[jj][ii] = dev_interp(Tt, Tv, tq);
        }
    }
    __syncthreads();

#pragma unroll 1
    for (int q = 0; q < 8; ++q) {
        const int n = 8 * g + q;
        float* row = E0 + (size_t)n * NS;
        if (n == 0) {
            for (int i = t; i < NS; i += 256) row[i] = iv[i];
            continue;
        }
        const int p = ((n - 1) & 7) + 1;
        const float* cvp = cv + (size_t)(p - 1) * NS;
        for (int i = t; i < NS; i += 256) {
            float acc = cvp[i];
            for (int jj = 0; jj < p; ++jj) {
                const float* sj = s[q + 7 - jj];
                const float* base = vw + (size_t)jj * 5 * NS;
                acc += sj[0] * base[i]          + sj[1] * base[NS + i]
                     + sj[2] * base[2 * NS + i] + sj[3] * base[3 * NS + i];
            }
            row[i] = acc;
        }
    }
}

// ---------------- fused split-K anchor BK edge + last-block reduce ----------------
__global__ void __launch_bounds__(128, 4) k_bk_sk(
    float* __restrict__ V, const float* __restrict__ W,
    float* __restrict__ part, int* __restrict__ ctr,
    int S, int aoff, int boff, int cnt)
{
    __shared__ float As[16][132];
    __shared__ float Bs[16][68];
    __shared__ int s_old;

    const int t  = threadIdx.x;
    const int tx = t & 7;
    const int ty = t >> 3;
    const int r0 = blockIdx.y * 128;
    const int c0 = blockIdx.x * 64;
    const int z  = blockIdx.z;
    const int kb = z * 128;

    const int  ar  = t >> 2;
    const int  ac4 = (t & 3) * 4;
    long gr[4]; bool v[4];
#pragma unroll
    for (int g = 0; g < 4; g++) {
        int lo = r0 + ar + 32 * g;
        v[g]  = lo < cnt;
        gr[g] = (long)lo * S + aoff;
    }

    const int br  = t >> 4;
    const int bc4 = (t & 15) * 4;

    unsigned long long acc[8][4];
#pragma unroll
    for (int m = 0; m < 8; m++)
#pragma unroll
        for (int p = 0; p < 4; p++) acc[m][p] = 0ull;

    const float4 f4z = make_float4(0.f, 0.f, 0.f, 0.f);
    float4 av[4], b0, b1;
#pragma unroll
    for (int g = 0; g < 4; g++)
        av[g] = v[g] ? *(const float4*)(V + gr[g] * NS + kb + ac4) : f4z;
    b0 = *(const float4*)(W + (size_t)(kb + br) * NS + c0 + bc4);
    b1 = *(const float4*)(W + (size_t)(kb + br + 8) * NS + c0 + bc4);

    for (int it = 0; it < 8; ++it) {
#pragma unroll
        for (int g = 0; g < 4; g++) {
            As[ac4 + 0][ar + 32 * g] = av[g].x;
            As[ac4 + 1][ar + 32 * g] = av[g].y;
            As[ac4 + 2][ar + 32 * g] = av[g].z;
            As[ac4 + 3][ar + 32 * g] = av[g].w;
        }
        *(float4*)&Bs[br][bc4]     = b0;
        *(float4*)&Bs[br + 8][bc4] = b1;
        __syncthreads();

        if (it < 7) {
            const int k0 = kb + (it + 1) * 16;
#pragma unroll
            for (int g = 0; g < 4; g++)
                av[g] = v[g] ? *(const float4*)(V + gr[g] * NS + k0 + ac4) : f4z;
            b0 = *(const float4*)(W + (size_t)(k0 + br) * NS + c0 + bc4);
            b1 = *(const float4*)(W + (size_t)(k0 + br + 8) * NS + c0 + bc4);
        }

#pragma unroll
        for (int kk = 0; kk < 16; ++kk) {
            float a[8];
            *(float4*)&a[0] = *(const float4*)&As[kk][ty * 8];
            *(float4*)&a[4] = *(const float4*)&As[kk][ty * 8 + 4];
            ulonglong2 bp0 = *(const ulonglong2*)&Bs[kk][tx * 8];
            ulonglong2 bp1 = *(const ulonglong2*)&Bs[kk][tx * 8 + 4];
            unsigned long long bv[4] = {bp0.x, bp0.y, bp1.x, bp1.y};
#pragma unroll
            for (int m = 0; m < 8; m++) {
                unsigned long long avv;
                asm("mov.b64 %0, {%1, %1};" : "=l"(avv) : "f"(a[m]));
#pragma unroll
                for (int p = 0; p < 4; p++)
                    asm("fma.rn.f32x2 %0, %1, %2, %0;"
                        : "+l"(acc[m][p]) : "l"(avv), "l"(bv[p]));
            }
        }
        __syncthreads();
    }

#pragma unroll
    for (int m = 0; m < 8; m++) {
        const int r = r0 + ty * 8 + m;
        if (r < cnt) {
            float c[8];
#pragma unroll
            for (int p = 0; p < 4; p++)
                asm("mov.b64 {%0, %1}, %2;"
                    : "=f"(c[2 * p]), "=f"(c[2 * p + 1]) : "l"(acc[m][p]));
            float* prow = part + ((size_t)z * SKROWS + r) * NS + c0 + tx * 8;
            *(float4*)prow       = make_float4(c[0], c[1], c[2], c[3]);
            *(float4*)(prow + 4) = make_float4(c[4], c[5], c[6], c[7]);
        }
    }

    // last of the 4 k-split blocks reduces this tile into V (in place, disjoint rows)
    __threadfence();
    __syncthreads();
    if (t == 0) s_old = atomicAdd(&ctr[blockIdx.y * 8 + blockIdx.x], 1);
    __syncthreads();
    if (s_old == 3) {
        __threadfence();
        for (int i = t; i < 128 * 16; i += 128) {     // 128 rows x 16 float4
            const int r = r0 + (i >> 4);
            if (r < cnt) {
                const int c4 = c0 + ((i & 15) << 2);
                float4 p0 = *(const float4*)(part + ((size_t)0 * SKROWS + r) * NS + c4);
                float4 p1 = *(const float4*)(part + ((size_t)1 * SKROWS + r) * NS + c4);
                float4 p2 = *(const float4*)(part + ((size_t)2 * SKROWS + r) * NS + c4);
                float4 p3 = *(const float4*)(part + ((size_t)3 * SKROWS + r) * NS + c4);
                float* dst = V + ((size_t)r * S + boff) * NS + c4;
                float4 d = *(const float4*)dst;
                d.x += (p0.x + p1.x) + (p2.x + p3.x);
                d.y += (p0.y + p1.y) + (p2.y + p3.y);
                d.z += (p0.z + p1.z) + (p2.z + p3.z);
                d.w += (p0.w + p1.w) + (p2.w + p3.w);
                *(float4*)dst = d;
            }
        }
    }
}

// ---------------- flat fill (verbatim R12): x[8r+q] = E[8r+q] + T_q x[8r] ----------------
__global__ void __launch_bounds__(128, 4) k_fillz(
    float* __restrict__ V, const float* __restrict__ Tb, int cnt)
{
    const int q = blockIdx.z + 1;
    const float* W = Tb + (size_t)q * NS2;

    __shared__ float As[16][132];
    __shared__ float Bs[16][68];

    const int t  = threadIdx.x;
    const int tx = t & 7;
    const int ty = t >> 3;
    const int r0 = blockIdx.y * 128;
    const int c0 = blockIdx.x * 64;

    const int  ar  = t >> 2;
    const int  ac4 = (t & 3) * 4;
    long gr[4]; bool v[4];
#pragma unroll
    for (int g = 0; g < 4; g++) {
        int lo = r0 + ar + 32 * g;
        v[g]  = lo < cnt;
        gr[g] = (long)lo * RAD;
    }

    const int br  = t >> 4;
    const int bc4 = (t & 15) * 4;

    unsigned long long acc[8][4];
#pragma unroll
    for (int m = 0; m < 8; m++)
#pragma unroll
        for (int p = 0; p < 4; p++) acc[m][p] = 0ull;

    const float4 f4z = make_float4(0.f, 0.f, 0.f, 0.f);
    float4 av[4], b0, b1;
#pragma unroll
    for (int g = 0; g < 4; g++)
        av[g] = v[g] ? *(const float4*)(V + gr[g] * NS + ac4) : f4z;
    b0 = *(const float4*)(W + (size_t)br * NS + c0 + bc4);
    b1 = *(const float4*)(W + (size_t)(br + 8) * NS + c0 + bc4);

    for (int it = 0; it < 32; ++it) {
#pragma unroll
        for (int g = 0; g < 4; g++) {
            As[ac4 + 0][ar + 32 * g] = av[g].x;
            As[ac4 + 1][ar + 32 * g] = av[g].y;
            As[ac4 + 2][ar + 32 * g] = av[g].z;
            As[ac4 + 3][ar + 32 * g] = av[g].w;
        }
        *(float4*)&Bs[br][bc4]     = b0;
        *(float4*)&Bs[br + 8][bc4] = b1;
        __syncthreads();

        if (it < 31) {
            const int k0 = (it + 1) * 16;
#pragma unroll
            for (int g = 0; g < 4; g++)
                av[g] = v[g] ? *(const float4*)(V + gr[g] * NS + k0 + ac4) : f4z;
            b0 = *(const float4*)(W + (size_t)(k0 + br) * NS + c0 + bc4);
            b1 = *(const float4*)(W + (size_t)(k0 + br + 8) * NS + c0 + bc4);
        }

#pragma unroll
        for (int kk = 0; kk < 16; ++kk) {
            float a[8];
            *(float4*)&a[0] = *(const float4*)&As[kk][ty * 8];
            *(float4*)&a[4] = *(const float4*)&As[kk][ty * 8 + 4];
            ulonglong2 bp0 = *(const ulonglong2*)&Bs[kk][tx * 8];
            ulonglong2 bp1 = *(const ulonglong2*)&Bs[kk][tx * 8 + 4];
            unsigned long long bv[4] = {bp0.x, bp0.y, bp1.x, bp1.y};
#pragma unroll
            for (int m = 0; m < 8; m++) {
                unsigned long long avv;
                asm("mov.b64 %0, {%1, %1};" : "=l"(avv) : "f"(a[m]));
#pragma unroll
                for (int p = 0; p < 4; p++)
                    asm("fma.rn.f32x2 %0, %1, %2, %0;"
                        : "+l"(acc[m][p]) : "l"(avv), "l"(bv[p]));
            }
        }
        __syncthreads();
    }

#pragma unroll
    for (int m = 0; m < 8; m++) {
        const int r = r0 + ty * 8 + m;
        if (r < cnt) {
            const long dr = (long)r * RAD + q;
            float* erow = V + dr * NS + c0 + tx * 8;
            float4 e0 = *(const float4*)erow;
            float4 e1 = *(const float4*)(erow + 4);
            float c[8];
#pragma unroll
            for (int p = 0; p < 4; p++)
                asm("mov.b64 {%0, %1}, %2;"
                    : "=f"(c[2 * p]), "=f"(c[2 * p + 1]) : "l"(acc[m][p]));
            float4 o0 = make_float4(c[0] + e0.x, c[1] + e0.y, c[2] + e0.z, c[3] + e0.w);
            float4 o1 = make_float4(c[4] + e1.x, c[5] + e1.y, c[6] + e1.z, c[7] + e1.w);
            *(float4*)erow       = o0;
            *(float4*)(erow + 4) = o1;
        }
    }
}

// ---------------- host orchestration (graph-capturable, alloc-free) ----------------
extern "C" void kernel_launch(void* const* d_in, const int* in_sizes, int n_in,
                              void* d_out, int out_size) {
    const float* A  = (const float*)d_in[0];
    const float* Bm = (const float*)d_in[1];
    const float* Q  = (const float*)d_in[2];
    const float* Tt = (const float*)d_in[3];
    const float* Tv = (const float*)d_in[4];
    const float* iv = (const float*)d_in[5];
    float* out = (float*)d_out;

    float *Lt, *G1, *G2, *Tb, *vec, *vw, *cv, *part;
    int* ctr;
    cudaGetSymbolAddress((void**)&Lt,   d_Lt);
    cudaGetSymbolAddress((void**)&G1,   d_G1);
    cudaGetSymbolAddress((void**)&G2,   d_G2);
    cudaGetSymbolAddress((void**)&Tb,   d_T);
    cudaGetSymbolAddress((void**)&vec,  d_vec);
    cudaGetSymbolAddress((void**)&vw,   d_vw);
    cudaGetSymbolAddress((void**)&cv,   d_cv);
    cudaGetSymbolAddress((void**)&part, d_part);
    cudaGetSymbolAddress((void**)&ctr,  d_ctr);

    // zero all per-launch tile counters (23 slices x 128)
    cudaMemsetAsync(ctr, 0, 32 * 128 * sizeof(int), 0);

    // Lt = (dt*A)^T
    k_tpose<<<1024, 256>>>(A, Lt);

    // forcing vectors w1..w4, v  (into vw[0])
    k_gh<<<2, 256>>>(Bm, Q, vec + 0 * NS, vec + 1 * NS);
    k_matvec2<<<512, 128>>>(A, vec + 0 * NS, vec + 1 * NS, vec + 2 * NS, vec + 5 * NS, DTC);
    k_matvec2<<<512, 128>>>(A, vec + 2 * NS, vec + 5 * NS, vec + 3 * NS, vec + 6 * NS, DTC);
    k_matvec2<<<512, 128>>>(A, vec + 3 * NS, vec + 6 * NS, vec + 4 * NS, vec + 7 * NS, DTC);
    k_combine<<<2, 256>>>(vec, vw);

    const dim3 gsk(8, 16, 4);

    // G1 = Lt^2 ; T1 = (I + Lt + G1/2) + G1 @ (Lt/6 + G1/24)
    k_gsk<<<gsk, 128>>>(Lt, Lt, part, G1, nullptr, ctr + 0 * 128);
    k_prep1<<<1024, 256>>>(Lt, G1, G2, Tb + 0 * (size_t)NS2);
    k_gsk<<<gsk, 128>>>(G1, G2, part, Tb + 1 * (size_t)NS2, Tb + 0 * (size_t)NS2, ctr + 1 * 128);

    // T2 ; {T3,T4} ; {T5..T8} ; T16 ; T32 ; T64 ; T128
    k_gsk<<<gsk, 128>>>(Tb + 1 * (size_t)NS2, Tb + 1 * (size_t)NS2, part,
                        Tb + 2 * (size_t)NS2, nullptr, ctr + 2 * 128);

    k_gskz<<<dim3(8, 16, 8), 128>>>(Tb, part, ctr + 3 * 128,
                                    1, 2, 0, 0, 2, 2, 0, 0, 3, 4, 0, 0);
    k_gskz<<<dim3(8, 16, 16), 128>>>(Tb, part, ctr + 5 * 128,
                                     1, 2, 3, 4, 4, 4, 4, 4, 5, 6, 7, 8);

    for (int s = 8; s <= 11; ++s)   // T16(9), T32(10), T64(11), T128(12)
        k_gsk<<<gsk, 128>>>(Tb + (size_t)s * NS2, Tb + (size_t)s * NS2, part,
                            Tb + (size_t)(s + 1) * NS2, nullptr, ctr + (s + 1) * 128);

    // vw[j] = [w,v] @ T_j (j=1..7) ; cv cumsums
    k_vw<<<dim3(2, 1, 7), 256>>>(Tb, vw);
    k_cv<<<2, 256>>>(vw, cv);

    // E0 with within-group-of-8 prefixes (grouped blocks)
    k_buildE0<<<NANCH, 256>>>(Tt, Tv, iv, vw, cv, out);

    // ---- anchor Brent-Kung over 2500 anchors (rows = 8*o), levels j=0..4
    int slice = 13;
    for (int j = 0; j < 5; ++j) {            // up-sweep
        const int Sa = 1 << (j + 1);
        const int cnt = NANCH >> (j + 1);
        const int Sm = RAD * Sa;
        const int aoff = RAD * ((1 << j) - 1);
        const int boff = RAD * (Sa - 1);
        dim3 gs(8, (cnt + 127) / 128, 4);
        k_bk_sk<<<gs, 128>>>(out, Tb + (size_t)(8 + j) * NS2, part, ctr + slice * 128,
                             Sm, aoff, boff, cnt);
        ++slice;
    }
    for (int j = 4; j >= 0; --j) {           // down-sweep
        const int Sa = 1 << (j + 1);
        const int boffa = Sa - 1 + (1 << j);
        const int cnt = (NANCH - 1 - boffa) / Sa + 1;
        const int Sm = RAD * Sa;
        const int aoff = RAD * (Sa - 1);
        const int boff = RAD * boffa;
        dim3 gs(8, (cnt + 127) / 128, 4);
        k_bk_sk<<<gs, 128>>>(out, Tb + (size_t)(8 + j) * NS2, part, ctr + slice * 128,
                             Sm, aoff, boff, cnt);
        ++slice;
    }

    // ---- flat fill: all non-anchor rows in one launch
    dim3 gf(8, (NANCH + 127) / 128, RAD - 1);
    k_fillz<<<gf, 128>>>(out, Tb, NANCH);
    // result in `out`
}

// round 16
// speedup vs baseline: 1.2830x; 1.0739x over previous
#include <cuda_runtime.h>

#define NS   512
#define NS2  (NS * NS)
#define TN   20000
#define ND   2000
#define DTC  30.0f
#define RAD  8          // fill radix (anchors every 8 rows)
#define NANCH 2500      // TN / RAD
#define SKROWS 1280     // split-K partial rows for anchor BK (max cnt = 1250)

// ---------------- static scratch (no allocations allowed) ----------------
__device__ float d_Lt[NS2];               // (dt*A)^T
__device__ float d_G1[NS2];               // Lt^2
__device__ float d_G2[NS2];               // H = Lt/6 + Lt^2/24
// T slots: 0 = Horner base ; 1..8 = (M^q)^T ; 9=T16,10=T32,11=T64,12=T128
__device__ float d_T[13][NS2];
__device__ float d_vec[8 * NS];
__device__ float d_vw[RAD * 5 * NS];      // vw[j] = M^j [w1..w4, v]
__device__ float d_cv[RAD * NS];          // cv[p-1] = sum_{j<p} M^j v
__device__ float d_part[16 * NS2];        // split-K partials (16.8 MB, reused)

// ---------------- small helpers ----------------
__global__ void k_tpose(const float* __restrict__ A, float* __restrict__ Lt) {
    int idx = blockIdx.x * blockDim.x + threadIdx.x;
    if (idx < NS2) {
        int i = idx >> 9, j = idx & 511;
        Lt[idx] = DTC * A[j * NS + i];
    }
}

__global__ void k_gh(const float* __restrict__ B, const float* __restrict__ Q,
                     float* __restrict__ g, float* __restrict__ h) {
    int i = blockIdx.x * blockDim.x + threadIdx.x;
    if (i < NS) {
        g[i] = B[i * 9];
        float s = 0.f;
#pragma unroll
        for (int m = 0; m < 8; m++) s += B[i * 9 + 1 + m] * Q[m];
        h[i] = s;
    }
}

__global__ void k_matvec2(const float* __restrict__ A,
                          const float* __restrict__ x1, const float* __restrict__ x2,
                          float* __restrict__ y1, float* __restrict__ y2, float scale) {
    __shared__ float red1[128], red2[128];
    int row = blockIdx.x;
    float s1 = 0.f, s2 = 0.f;
    for (int j = threadIdx.x; j < NS; j += 128) {
        float a = A[row * NS + j];
        s1 += a * x1[j];
        s2 += a * x2[j];
    }
    red1[threadIdx.x] = s1; red2[threadIdx.x] = s2;
    __syncthreads();
    for (int st = 64; st > 0; st >>= 1) {
        if (threadIdx.x < st) {
            red1[threadIdx.x] += red1[threadIdx.x + st];
            red2[threadIdx.x] += red2[threadIdx.x + st];
        }
        __syncthreads();
    }
    if (threadIdx.x == 0) { y1[row] = scale * red1[0]; y2[row] = scale * red2[0]; }
}

__global__ void k_combine(const float* __restrict__ vec, float* __restrict__ vw) {
    int i = blockIdx.x * blockDim.x + threadIdx.x;
    if (i >= NS) return;
    const float G   = vec[0 * NS + i], H   = vec[1 * NS + i];
    const float LG  = vec[2 * NS + i], L2G = vec[3 * NS + i], L3G = vec[4 * NS + i];
    const float LH  = vec[5 * NS + i], L2H = vec[6 * NS + i], L3H = vec[7 * NS + i];
    const float c = DTC / 8.0f;
    vw[0 * NS + i] = c * (G + LG + (L2G + L3G) * (1.0f / 3.0f));
    vw[1 * NS + i] = c * (3.0f * G + 2.0f * LG + L2G);
    vw[2 * NS + i] = c * (3.0f * G + LG);
    vw[3 * NS + i] = c * G;
    vw[4 * NS + i] = DTC * (H + 0.5f * LH + L2H * (1.0f / 6.0f) + L3H * (1.0f / 24.0f));
}

__global__ void k_prep1(const float* __restrict__ Lt, const float* __restrict__ G1,
                        float* __restrict__ H, float* __restrict__ base) {
    int idx = blockIdx.x * blockDim.x + threadIdx.x;
    if (idx < NS2) {
        int i = idx >> 9, j = idx & 511;
        float l = Lt[idx], g = G1[idx];
        H[idx]    = l * (1.0f / 6.0f) + g * (1.0f / 24.0f);
        base[idx] = l + 0.5f * g + (i == j ? 1.0f : 0.0f);
    }
}

// ---------------- split-K 512^3 GEMM partials (32x64 tile, K chunk 128) ----------------
__global__ void __launch_bounds__(128) k_gsk(
    const float* __restrict__ A, const float* __restrict__ B, float* __restrict__ part)
{
    __shared__ float As[16][36];
    __shared__ float Bs[16][68];
    const int t  = threadIdx.x;
    const int tx = t & 7, ty = t >> 3;
    const int r0 = blockIdx.y * 32, c0 = blockIdx.x * 64;
    const int kb = blockIdx.z * 128;

    const int ar = t >> 2, ac4 = (t & 3) * 4;
    const int br = t >> 4, bc4 = (t & 15) * 4;

    unsigned long long acc[2][4];
#pragma unroll
    for (int m = 0; m < 2; m++)
#pragma unroll
        for (int p = 0; p < 4; p++) acc[m][p] = 0ull;

    float4 av = *(const float4*)(A + (size_t)(r0 + ar) * NS + kb + ac4);
    float4 b0 = *(const float4*)(B + (size_t)(kb + br) * NS + c0 + bc4);
    float4 b1 = *(const float4*)(B + (size_t)(kb + br + 8) * NS + c0 + bc4);

    for (int it = 0; it < 8; ++it) {
        As[ac4 + 0][ar] = av.x; As[ac4 + 1][ar] = av.y;
        As[ac4 + 2][ar] = av.z; As[ac4 + 3][ar] = av.w;
        *(float4*)&Bs[br][bc4]     = b0;
        *(float4*)&Bs[br + 8][bc4] = b1;
        __syncthreads();
        if (it < 7) {
            const int k0 = kb + (it + 1) * 16;
            av = *(const float4*)(A + (size_t)(r0 + ar) * NS + k0 + ac4);
            b0 = *(const float4*)(B + (size_t)(k0 + br) * NS + c0 + bc4);
            b1 = *(const float4*)(B + (size_t)(k0 + br + 8) * NS + c0 + bc4);
        }
#pragma unroll
        for (int kk = 0; kk < 16; ++kk) {
            float a0 = As[kk][ty * 2 + 0];
            float a1 = As[kk][ty * 2 + 1];
            ulonglong2 bp0 = *(const ulonglong2*)&Bs[kk][tx * 8];
            ulonglong2 bp1 = *(const ulonglong2*)&Bs[kk][tx * 8 + 4];
            unsigned long long bv[4] = {bp0.x, bp0.y, bp1.x, bp1.y};
            unsigned long long av0, av1;
            asm("mov.b64 %0, {%1, %1};" : "=l"(av0) : "f"(a0));
            asm("mov.b64 %0, {%1, %1};" : "=l"(av1) : "f"(a1));
#pragma unroll
            for (int p = 0; p < 4; p++) {
                asm("fma.rn.f32x2 %0, %1, %2, %0;" : "+l"(acc[0][p]) : "l"(av0), "l"(bv[p]));
                asm("fma.rn.f32x2 %0, %1, %2, %0;" : "+l"(acc[1][p]) : "l"(av1), "l"(bv[p]));
            }
        }
        __syncthreads();
    }
    float* po = part + (size_t)blockIdx.z * NS2;
#pragma unroll
    for (int m = 0; m < 2; m++) {
        const int row = r0 + ty * 2 + m;
#pragma unroll
        for (int p = 0; p < 4; p++) {
            float lo, hi;
            asm("mov.b64 {%0, %1}, %2;" : "=f"(lo), "=f"(hi) : "l"(acc[m][p]));
            int col = c0 + tx * 8 + 2 * p;
            po[(size_t)row * NS + col]     = lo;
            po[(size_t)row * NS + col + 1] = hi;
        }
    }
}

// batched split-K over T slots: item = z>>2, ksplit = z&3
__global__ void __launch_bounds__(128) k_gskz(
    float* __restrict__ Tb, float* __restrict__ part,
    int a0, int a1, int a2, int a3, int b0s, int b1s, int b2s, int b3s)
{
    const int item = blockIdx.z >> 2;
    const int ks   = blockIdx.z & 3;
    const int asl  = (item == 0) ? a0 : (item == 1) ? a1 : (item == 2) ? a2 : a3;
    const int bsl  = (item == 0) ? b0s : (item == 1) ? b1s : (item == 2) ? b2s : b3s;
    const float* A = Tb + (size_t)asl * NS2;
    const float* B = Tb + (size_t)bsl * NS2;

    __shared__ float As[16][36];
    __shared__ float Bs[16][68];
    const int t  = threadIdx.x;
    const int tx = t & 7, ty = t >> 3;
    const int r0 = blockIdx.y * 32, c0 = blockIdx.x * 64;
    const int kb = ks * 128;

    const int ar = t >> 2, ac4 = (t & 3) * 4;
    const int br = t >> 4, bc4 = (t & 15) * 4;

    unsigned long long acc[2][4];
#pragma unroll
    for (int m = 0; m < 2; m++)
#pragma unroll
        for (int p = 0; p < 4; p++) acc[m][p] = 0ull;

    float4 av = *(const float4*)(A + (size_t)(r0 + ar) * NS + kb + ac4);
    float4 b0 = *(const float4*)(B + (size_t)(kb + br) * NS + c0 + bc4);
    float4 b1 = *(const float4*)(B + (size_t)(kb + br + 8) * NS + c0 + bc4);

    for (int it = 0; it < 8; ++it) {
        As[ac4 + 0][ar] = av.x; As[ac4 + 1][ar] = av.y;
        As[ac4 + 2][ar] = av.z; As[ac4 + 3][ar] = av.w;
        *(float4*)&Bs[br][bc4]     = b0;
        *(float4*)&Bs[br + 8][bc4] = b1;
        __syncthreads();
        if (it < 7) {
            const int k0 = kb + (it + 1) * 16;
            av = *(const float4*)(A + (size_t)(r0 + ar) * NS + k0 + ac4);
            b0 = *(const float4*)(B + (size_t)(k0 + br) * NS + c0 + bc4);
            b1 = *(const float4*)(B + (size_t)(k0 + br + 8) * NS + c0 + bc4);
        }
#pragma unroll
        for (int kk = 0; kk < 16; ++kk) {
            float a0f = As[kk][ty * 2 + 0];
            float a1f = As[kk][ty * 2 + 1];
            ulonglong2 bp0 = *(const ulonglong2*)&Bs[kk][tx * 8];
            ulonglong2 bp1 = *(const ulonglong2*)&Bs[kk][tx * 8 + 4];
            unsigned long long bv[4] = {bp0.x, bp0.y, bp1.x, bp1.y};
            unsigned long long av0, av1;
            asm("mov.b64 %0, {%1, %1};" : "=l"(av0) : "f"(a0f));
            asm("mov.b64 %0, {%1, %1};" : "=l"(av1) : "f"(a1f));
#pragma unroll
            for (int p = 0; p < 4; p++) {
                asm("fma.rn.f32x2 %0, %1, %2, %0;" : "+l"(acc[0][p]) : "l"(av0), "l"(bv[p]));
                asm("fma.rn.f32x2 %0, %1, %2, %0;" : "+l"(acc[1][p]) : "l"(av1), "l"(bv[p]));
            }
        }
        __syncthreads();
    }
    float* po = part + (size_t)(item * 4 + ks) * NS2;
#pragma unroll
    for (int m = 0; m < 2; m++) {
        const int row = r0 + ty * 2 + m;
#pragma unroll
        for (int p = 0; p < 4; p++) {
            float lo, hi;
            asm("mov.b64 {%0, %1}, %2;" : "=f"(lo), "=f"(hi) : "l"(acc[m][p]));
            int col = c0 + tx * 8 + 2 * p;
            po[(size_t)row * NS + col]     = lo;
            po[(size_t)row * NS + col + 1] = hi;
        }
    }
}

// C = (base?) + sum of 4 K-partials (deterministic fixed order)
__global__ void k_gred(float* __restrict__ C, const float* __restrict__ part,
                       const float* __restrict__ base) {
    int idx = blockIdx.x * 256 + threadIdx.x;
    size_t o = (size_t)idx * 4;
    float4 p0 = *(const float4*)(part + 0 * (size_t)NS2 + o);
    float4 p1 = *(const float4*)(part + 1 * (size_t)NS2 + o);
    float4 p2 = *(const float4*)(part + 2 * (size_t)NS2 + o);
    float4 p3 = *(const float4*)(part + 3 * (size_t)NS2 + o);
    float4 b = base ? *(const float4*)(base + o) : make_float4(0.f, 0.f, 0.f, 0.f);
    float4 r;
    r.x = b.x + (p0.x + p1.x) + (p2.x + p3.x);
    r.y = b.y + (p0.y + p1.y) + (p2.y + p3.y);
    r.z = b.z + (p0.z + p1.z) + (p2.z + p3.z);
    r.w = b.w + (p0.w + p1.w) + (p2.w + p3.w);
    *(float4*)(C + o) = r;
}

__global__ void k_gredz(float* __restrict__ Tb, const float* __restrict__ part,
                        int d0, int d1, int d2, int d3) {
    const int item = blockIdx.y;
    const int dsl  = (item == 0) ? d0 : (item == 1) ? d1 : (item == 2) ? d2 : d3;
    int idx = blockIdx.x * 256 + threadIdx.x;
    size_t o = (size_t)idx * 4;
    const float* p = part + (size_t)(item * 4) * NS2;
    float4 p0 = *(const float4*)(p + 0 * (size_t)NS2 + o);
    float4 p1 = *(const float4*)(p + 1 * (size_t)NS2 + o);
    float4 p2 = *(const float4*)(p + 2 * (size_t)NS2 + o);
    float4 p3 = *(const float4*)(p + 3 * (size_t)NS2 + o);
    float4 r;
    r.x = (p0.x + p1.x) + (p2.x + p3.x);
    r.y = (p0.y + p1.y) + (p2.y + p3.y);
    r.z = (p0.z + p1.z) + (p2.z + p3.z);
    r.w = (p0.w + p1.w) + (p2.w + p3.w);
    *(float4*)(Tb + (size_t)dsl * NS2 + o) = r;
}

// ---------------- vw[j] = [w1..w4,v] @ T_j (j=1..7, batched) ----------------
__global__ void k_vw(const float* __restrict__ Tb, float* __restrict__ vw) {
    const int j = blockIdx.z + 1;
    const float* T = Tb + (size_t)j * NS2;
    const int c = blockIdx.x * 256 + threadIdx.x;

    __shared__ float v0s[5 * NS];
    for (int i = threadIdx.x; i < 5 * NS; i += 256) v0s[i] = vw[i];
    __syncthreads();

    float acc0 = 0.f, acc1 = 0.f, acc2 = 0.f, acc3 = 0.f, acc4 = 0.f;
    for (int k = 0; k < NS; ++k) {
        float tk = T[(size_t)k * NS + c];
        acc0 += v0s[0 * NS + k] * tk;
        acc1 += v0s[1 * NS + k] * tk;
        acc2 += v0s[2 * NS + k] * tk;
        acc3 += v0s[3 * NS + k] * tk;
        acc4 += v0s[4 * NS + k] * tk;
    }
    float* o = vw + (size_t)j * 5 * NS;
    o[0 * NS + c] = acc0; o[1 * NS + c] = acc1; o[2 * NS + c] = acc2;
    o[3 * NS + c] = acc3; o[4 * NS + c] = acc4;
}

__global__ void k_cv(const float* __restrict__ vw, float* __restrict__ cv) {
    int c = blockIdx.x * 256 + threadIdx.x;
    if (c >= NS) return;
    float acc = 0.f;
    for (int j = 0; j < RAD; ++j) {
        acc += vw[((size_t)j * 5 + 4) * NS + c];
        cv[(size_t)j * NS + c] = acc;
    }
}

// ---------------- grouped E0: one block per group of 8 rows ----------------
__device__ __forceinline__ float dev_interp(const float* __restrict__ Tt,
                                            const float* __restrict__ Tv, float tq) {
    if (tq <= Tt[0])      return Tv[0];
    if (tq >= Tt[ND - 1]) return Tv[ND - 1];
    int lo = 0, hi = ND - 1;
    while (hi - lo > 1) {
        int mid = (lo + hi) >> 1;
        if (Tt[mid] <= tq) lo = mid; else hi = mid;
    }
    float x0 = Tt[lo], x1 = Tt[lo + 1];
    return Tv[lo] + (tq - x0) * (Tv[lo + 1] - Tv[lo]) / (x1 - x0);
}

__global__ void k_buildE0(const float* __restrict__ Tt, const float* __restrict__ Tv,
                          const float* __restrict__ iv, const float* __restrict__ vw,
                          const float* __restrict__ cv, float* __restrict__ E0)
{
    const int g = blockIdx.x;       // rows 8g..8g+7
    const int t = threadIdx.x;      // 256
    __shared__ float s[15][4];      // d indices 8g-8 .. 8g+6
    const int d0 = 8 * g - 8;
    if (t < 60) {
        int jj = t >> 2, ii = t & 3;
        int d = d0 + jj;
        if (d >= 0) {
            float tq = (float)d * DTC + (float)ii * 10.0f;
            s[jj][ii] = dev_interp(Tt, Tv, tq);
        }
    }
    __syncthreads();

#pragma unroll 1
    for (int q = 0; q < 8; ++q) {
        const int n = 8 * g + q;
        float* row = E0 + (size_t)n * NS;
        if (n == 0) {
            for (int i = t; i < NS; i += 256) row[i] = iv[i];
            continue;
        }
        const int p = ((n - 1) & 7) + 1;
        const float* cvp = cv + (size_t)(p - 1) * NS;
        for (int i = t; i < NS; i += 256) {
            float acc = cvp[i];
            for (int jj = 0; jj < p; ++jj) {
                const float* sj = s[q + 7 - jj];
                const float* base = vw + (size_t)jj * 5 * NS;
                acc += sj[0] * base[i]          + sj[1] * base[NS + i]
                     + sj[2] * base[2 * NS + i] + sj[3] * base[3 * NS + i];
            }
            row[i] = acc;
        }
    }
}

// ---- shared macros for the double-buffered 128x64 GEMV bodies ----
#define LOADREG(K0)                                                              \
    do {                                                                         \
        _Pragma("unroll")                                                        \
        for (int g = 0; g < 4; g++)                                              \
            av[g] = v[g] ? *(const float4*)(Vv + gr[g] * NS + (K0) + ac4) : f4z; \
        b0 = *(const float4*)(W + (size_t)((K0) + br) * NS + c0 + bc4);          \
        b1 = *(const float4*)(W + (size_t)((K0) + br + 8) * NS + c0 + bc4);      \
    } while (0)

#define STORE_BUF(AS, BS)                                                        \
    do {                                                                         \
        _Pragma("unroll")                                                        \
        for (int g = 0; g < 4; g++) {                                            \
            AS[ac4 + 0][ar + 32 * g] = av[g].x;                                  \
            AS[ac4 + 1][ar + 32 * g] = av[g].y;                                  \
            AS[ac4 + 2][ar + 32 * g] = av[g].z;                                  \
            AS[ac4 + 3][ar + 32 * g] = av[g].w;                                  \
        }                                                                        \
        *(float4*)&BS[br][bc4]     = b0;                                         \
        *(float4*)&BS[br + 8][bc4] = b1;                                         \
    } while (0)

#define COMPUTE_BUF(AS, BS)                                                      \
    do {                                                                         \
        _Pragma("unroll")                                                        \
        for (int kk = 0; kk < 16; ++kk) {                                        \
            float a[8];                                                          \
            *(float4*)&a[0] = *(const float4*)&AS[kk][ty * 8];                   \
            *(float4*)&a[4] = *(const float4*)&AS[kk][ty * 8 + 4];               \
            ulonglong2 bp0 = *(const ulonglong2*)&BS[kk][tx * 8];                \
            ulonglong2 bp1 = *(const ulonglong2*)&BS[kk][tx * 8 + 4];            \
            unsigned long long bv[4] = {bp0.x, bp0.y, bp1.x, bp1.y};             \
            _Pragma("unroll")                                                    \
            for (int m = 0; m < 8; m++) {                                        \
                unsigned long long avv;                                          \
                asm("mov.b64 %0, {%1, %1};" : "=l"(avv) : "f"(a[m]));            \
                _Pragma("unroll")                                                \
                for (int p = 0; p < 4; p++)                                      \
                    asm("fma.rn.f32x2 %0, %1, %2, %0;"                           \
                        : "+l"(acc[m][p]) : "l"(avv), "l"(bv[p]));               \
            }                                                                    \
        }                                                                        \
    } while (0)

// ---------------- split-K anchor BK edge (double-buffered SMEM) ----------------
__global__ void __launch_bounds__(128, 4) k_bk_sk(
    const float* __restrict__ V, const float* __restrict__ W,
    float* __restrict__ part, int S, int aoff, int cnt)
{
    __shared__ float As0[16][132], As1[16][132];
    __shared__ float Bs0[16][68],  Bs1[16][68];

    const int t  = threadIdx.x;
    const int tx = t & 7;
    const int ty = t >> 3;
    const int r0 = blockIdx.y * 128;
    const int c0 = blockIdx.x * 64;
    const int z  = blockIdx.z;
    const int kb = z * 128;

    const int  ar  = t >> 2;
    const int  ac4 = (t & 3) * 4;
    long gr[4]; bool v[4];
#pragma unroll
    for (int g = 0; g < 4; g++) {
        int lo = r0 + ar + 32 * g;
        v[g]  = lo < cnt;
        gr[g] = (long)lo * S + aoff;
    }

    const int br  = t >> 4;
    const int bc4 = (t & 15) * 4;
    const float* Vv = V;

    unsigned long long acc[8][4];
#pragma unroll
    for (int m = 0; m < 8; m++)
#pragma unroll
        for (int p = 0; p < 4; p++) acc[m][p] = 0ull;

    const float4 f4z = make_float4(0.f, 0.f, 0.f, 0.f);
    float4 av[4], b0, b1;

    LOADREG(kb);
    STORE_BUF(As0, Bs0);
    __syncthreads();

#pragma unroll 1
    for (int it2 = 0; it2 < 4; ++it2) {
        // even phase: compute chunk 2*it2 (buf0), stage chunk 2*it2+1 -> buf1
        LOADREG(kb + (2 * it2 + 1) * 16);
        COMPUTE_BUF(As0, Bs0);
        STORE_BUF(As1, Bs1);
        __syncthreads();
        // odd phase: compute chunk 2*it2+1 (buf1), stage chunk 2*it2+2 -> buf0
        if (it2 < 3) LOADREG(kb + (2 * it2 + 2) * 16);
        COMPUTE_BUF(As1, Bs1);
        if (it2 < 3) STORE_BUF(As0, Bs0);
        __syncthreads();
    }

#pragma unroll
    for (int m = 0; m < 8; m++) {
        const int r = r0 + ty * 8 + m;
        if (r < cnt) {
            float c[8];
#pragma unroll
            for (int p = 0; p < 4; p++)
                asm("mov.b64 {%0, %1}, %2;"
                    : "=f"(c[2 * p]), "=f"(c[2 * p + 1]) : "l"(acc[m][p]));
            float* prow = part + ((size_t)z * SKROWS + r) * NS + c0 + tx * 8;
            *(float4*)prow       = make_float4(c[0], c[1], c[2], c[3]);
            *(float4*)(prow + 4) = make_float4(c[4], c[5], c[6], c[7]);
        }
    }
}

__global__ void k_bk_red(float* __restrict__ V, const float* __restrict__ part,
                         int S, int boff, int cnt)
{
    int idx = blockIdx.x * 256 + threadIdx.x;
    int total = cnt * (NS / 4);
    if (idx >= total) return;
    int r  = idx / (NS / 4);
    int c4 = (idx - r * (NS / 4)) * 4;
    float4 p0 = *(const float4*)(part + ((size_t)0 * SKROWS + r) * NS + c4);
    float4 p1 = *(const float4*)(part + ((size_t)1 * SKROWS + r) * NS + c4);
    float4 p2 = *(const float4*)(part + ((size_t)2 * SKROWS + r) * NS + c4);
    float4 p3 = *(const float4*)(part + ((size_t)3 * SKROWS + r) * NS + c4);
    float* dst = V + ((size_t)r * S + boff) * NS + c4;
    float4 d = *(const float4*)dst;
    d.x += (p0.x + p1.x) + (p2.x + p3.x);
    d.y += (p0.y + p1.y) + (p2.y + p3.y);
    d.z += (p0.z + p1.z) + (p2.z + p3.z);
    d.w += (p0.w + p1.w) + (p2.w + p3.w);
    *(float4*)dst = d;
}

// ---------------- flat fill (double-buffered SMEM): x[8r+q] = E[8r+q] + T_q x[8r] ----------------
__global__ void __launch_bounds__(128, 4) k_fillz(
    float* __restrict__ V, const float* __restrict__ Tb, int cnt)
{
    const int q = blockIdx.z + 1;
    const float* W = Tb + (size_t)q * NS2;

    __shared__ float As0[16][132], As1[16][132];
    __shared__ float Bs0[16][68],  Bs1[16][68];

    const int t  = threadIdx.x;
    const int tx = t & 7;
    const int ty = t >> 3;
    const int r0 = blockIdx.y * 128;
    const int c0 = blockIdx.x * 64;

    const int  ar  = t >> 2;
    const int  ac4 = (t & 3) * 4;
    long gr[4]; bool v[4];
#pragma unroll
    for (int g = 0; g < 4; g++) {
        int lo = r0 + ar + 32 * g;
        v[g]  = lo < cnt;
        gr[g] = (long)lo * RAD;
    }

    const int br  = t >> 4;
    const int bc4 = (t & 15) * 4;
    const float* Vv = V;

    unsigned long long acc[8][4];
#pragma unroll
    for (int m = 0; m < 8; m++)
#pragma unroll
        for (int p = 0; p < 4; p++) acc[m][p] = 0ull;

    const float4 f4z = make_float4(0.f, 0.f, 0.f, 0.f);
    float4 av[4], b0, b1;

    LOADREG(0);
    STORE_BUF(As0, Bs0);
    __syncthreads();

#pragma unroll 1
    for (int it2 = 0; it2 < 16; ++it2) {
        // even phase: compute chunk 2*it2 (buf0), stage chunk 2*it2+1 -> buf1
        LOADREG((2 * it2 + 1) * 16);
        COMPUTE_BUF(As0, Bs0);
        STORE_BUF(As1, Bs1);
        __syncthreads();
        // odd phase: compute chunk 2*it2+1 (buf1), stage chunk 2*it2+2 -> buf0
        if (it2 < 15) LOADREG((2 * it2 + 2) * 16);
        COMPUTE_BUF(As1, Bs1);
        if (it2 < 15) STORE_BUF(As0, Bs0);
        __syncthreads();
    }

#pragma unroll
    for (int m = 0; m < 8; m++) {
        const int r = r0 + ty * 8 + m;
        if (r < cnt) {
            const long dr = (long)r * RAD + q;
            float* erow = V + dr * NS + c0 + tx * 8;
            float4 e0 = *(const float4*)erow;
            float4 e1 = *(const float4*)(erow + 4);
            float c[8];
#pragma unroll
            for (int p = 0; p < 4; p++)
                asm("mov.b64 {%0, %1}, %2;"
                    : "=f"(c[2 * p]), "=f"(c[2 * p + 1]) : "l"(acc[m][p]));
            float4 o0 = make_float4(c[0] + e0.x, c[1] + e0.y, c[2] + e0.z, c[3] + e0.w);
            float4 o1 = make_float4(c[4] + e1.x, c[5] + e1.y, c[6] + e1.z, c[7] + e1.w);
            *(float4*)erow       = o0;
            *(float4*)(erow + 4) = o1;
        }
    }
}

// ---------------- host orchestration (graph-capturable, alloc-free) ----------------
extern "C" void kernel_launch(void* const* d_in, const int* in_sizes, int n_in,
                              void* d_out, int out_size) {
    const float* A  = (const float*)d_in[0];
    const float* Bm = (const float*)d_in[1];
    const float* Q  = (const float*)d_in[2];
    const float* Tt = (const float*)d_in[3];
    const float* Tv = (const float*)d_in[4];
    const float* iv = (const float*)d_in[5];
    float* out = (float*)d_out;

    float *Lt, *G1, *G2, *Tb, *vec, *vw, *cv, *part;
    cudaGetSymbolAddress((void**)&Lt,   d_Lt);
    cudaGetSymbolAddress((void**)&G1,   d_G1);
    cudaGetSymbolAddress((void**)&G2,   d_G2);
    cudaGetSymbolAddress((void**)&Tb,   d_T);
    cudaGetSymbolAddress((void**)&vec,  d_vec);
    cudaGetSymbolAddress((void**)&vw,   d_vw);
    cudaGetSymbolAddress((void**)&cv,   d_cv);
    cudaGetSymbolAddress((void**)&part, d_part);

    // Lt = (dt*A)^T
    k_tpose<<<1024, 256>>>(A, Lt);

    // forcing vectors w1..w4, v  (into vw[0])
    k_gh<<<2, 256>>>(Bm, Q, vec + 0 * NS, vec + 1 * NS);
    k_matvec2<<<512, 128>>>(A, vec + 0 * NS, vec + 1 * NS, vec + 2 * NS, vec + 5 * NS, DTC);
    k_matvec2<<<512, 128>>>(A, vec + 2 * NS, vec + 5 * NS, vec + 3 * NS, vec + 6 * NS, DTC);
    k_matvec2<<<512, 128>>>(A, vec + 3 * NS, vec + 6 * NS, vec + 4 * NS, vec + 7 * NS, DTC);
    k_combine<<<2, 256>>>(vec, vw);

    const dim3 gsk(8, 16, 4);
    const int RB = NS2 / 4 / 256;  // 256 blocks for full-matrix reduce

    // G1 = Lt^2 ; T1 = (I + Lt + G1/2) + G1 @ (Lt/6 + G1/24)
    k_gsk<<<gsk, 128>>>(Lt, Lt, part);
    k_gred<<<RB, 256>>>(G1, part, nullptr);
    k_prep1<<<1024, 256>>>(Lt, G1, G2, Tb + 0 * (size_t)NS2);
    k_gsk<<<gsk, 128>>>(G1, G2, part);
    k_gred<<<RB, 256>>>(Tb + 1 * (size_t)NS2, part, Tb + 0 * (size_t)NS2);

    // T2 ; {T3,T4} ; {T5..T8} ; T16 ; T32 ; T64 ; T128
    k_gsk<<<gsk, 128>>>(Tb + 1 * (size_t)NS2, Tb + 1 * (size_t)NS2, part);
    k_gred<<<RB, 256>>>(Tb + 2 * (size_t)NS2, part, nullptr);

    k_gskz<<<dim3(8, 16, 8), 128>>>(Tb, part, 1, 2, 0, 0, 2, 2, 0, 0);
    k_gredz<<<dim3(RB, 2), 256>>>(Tb, part, 3, 4, 0, 0);

    k_gskz<<<dim3(8, 16, 16), 128>>>(Tb, part, 1, 2, 3, 4, 4, 4, 4, 4);
    k_gredz<<<dim3(RB, 4), 256>>>(Tb, part, 5, 6, 7, 8);

    for (int s = 8; s <= 11; ++s) {  // T16(9), T32(10), T64(11), T128(12)
        k_gsk<<<gsk, 128>>>(Tb + (size_t)s * NS2, Tb + (size_t)s * NS2, part);
        k_gred<<<RB, 256>>>(Tb + (size_t)(s + 1) * NS2, part, nullptr);
    }

    // vw[j] = [w,v] @ T_j (j=1..7) ; cv cumsums
    k_vw<<<dim3(2, 1, 7), 256>>>(Tb, vw);
    k_cv<<<2, 256>>>(vw, cv);

    // E0 with within-group-of-8 prefixes (grouped blocks)
    k_buildE0<<<NANCH, 256>>>(Tt, Tv, iv, vw, cv, out);

    // ---- anchor Brent-Kung over 2500 anchors (rows = 8*o), levels j=0..4
    for (int j = 0; j < 5; ++j) {            // up-sweep
        const int Sa = 1 << (j + 1);
        const int cnt = NANCH >> (j + 1);
        const int Sm = RAD * Sa;
        const int aoff = RAD * ((1 << j) - 1);
        const int boff = RAD * (Sa - 1);
        dim3 gs(8, (cnt + 127) / 128, 4);
        k_bk_sk<<<gs, 128>>>(out, Tb + (size_t)(8 + j) * NS2, part, Sm, aoff, cnt);
        k_bk_red<<<(cnt * (NS / 4) + 255) / 256, 256>>>(out, part, Sm, boff, cnt);
    }
    for (int j = 4; j >= 0; --j) {           // down-sweep
        const int Sa = 1 << (j + 1);
        const int boffa = Sa - 1 + (1 << j);
        const int cnt = (NANCH - 1 - boffa) / Sa + 1;
        const int Sm = RAD * Sa;
        const int aoff = RAD * (Sa - 1);
        const int boff = RAD * boffa;
        dim3 gs(8, (cnt + 127) / 128, 4);
        k_bk_sk<<<gs, 128>>>(out, Tb + (size_t)(8 + j) * NS2, part, Sm, aoff, cnt);
        k_bk_red<<<(cnt * (NS / 4) + 255) / 256, 256>>>(out, part, Sm, boff, cnt);
    }

    // ---- flat fill: all non-anchor rows in one launch
    dim3 gf(8, (NANCH + 127) / 128, RAD - 1);
    k_fillz<<<gf, 128>>>(out, Tb, NANCH);
    // result in `out`
}

// round 17
// speedup vs baseline: 1.3000x; 1.0132x over previous
#include <cuda_runtime.h>

#define NS   512
#define NS2  (NS * NS)
#define TN   20000
#define ND   2000
#define DTC  30.0f
#define RAD  8          // fill radix (anchors every 8 rows)
#define NANCH 2500      // TN / RAD
#define SKROWS 1280     // split-K partial rows for anchor BK (max cnt = 1250)

// ---------------- static scratch (no allocations allowed) ----------------
__device__ float d_Lt[NS2];               // (dt*A)^T
__device__ float d_G1[NS2];               // Lt^2
__device__ float d_G2[NS2];               // H = Lt/6 + Lt^2/24
// T slots: 0 = Horner base ; 1..8 = (M^q)^T ; 9=T16,10=T32,11=T64,12=T128
__device__ float d_T[13][NS2];
__device__ float d_vec[8 * NS];
__device__ float d_vw[RAD * 5 * NS];      // vw[j] = M^j [w1..w4, v]
__device__ float d_cv[RAD * NS];          // cv[p-1] = sum_{j<p} M^j v
__device__ float d_part[16 * NS2];        // split-K partials (16.8 MB, reused)

// ---------------- fused: Lt = (dt*A)^T  +  g/h build (blocks >= 1024) ----------------
__global__ void k_tpose_gh(const float* __restrict__ A, float* __restrict__ Lt,
                           const float* __restrict__ B, const float* __restrict__ Q,
                           float* __restrict__ g, float* __restrict__ h) {
    if (blockIdx.x < 1024) {
        int idx = blockIdx.x * 256 + threadIdx.x;
        int i = idx >> 9, j = idx & 511;
        Lt[idx] = DTC * A[j * NS + i];
    } else {
        int i = (blockIdx.x - 1024) * 256 + threadIdx.x;
        if (i < NS) {
            g[i] = B[i * 9];
            float s = 0.f;
#pragma unroll
            for (int m = 0; m < 8; m++) s += B[i * 9 + 1 + m] * Q[m];
            h[i] = s;
        }
    }
}

__global__ void k_matvec2(const float* __restrict__ A,
                          const float* __restrict__ x1, const float* __restrict__ x2,
                          float* __restrict__ y1, float* __restrict__ y2, float scale) {
    __shared__ float red1[128], red2[128];
    int row = blockIdx.x;
    float s1 = 0.f, s2 = 0.f;
    for (int j = threadIdx.x; j < NS; j += 128) {
        float a = A[row * NS + j];
        s1 += a * x1[j];
        s2 += a * x2[j];
    }
    red1[threadIdx.x] = s1; red2[threadIdx.x] = s2;
    __syncthreads();
    for (int st = 64; st > 0; st >>= 1) {
        if (threadIdx.x < st) {
            red1[threadIdx.x] += red1[threadIdx.x + st];
            red2[threadIdx.x] += red2[threadIdx.x + st];
        }
        __syncthreads();
    }
    if (threadIdx.x == 0) { y1[row] = scale * red1[0]; y2[row] = scale * red2[0]; }
}

__global__ void k_combine(const float* __restrict__ vec, float* __restrict__ vw) {
    int i = blockIdx.x * blockDim.x + threadIdx.x;
    if (i >= NS) return;
    const float G   = vec[0 * NS + i], H   = vec[1 * NS + i];
    const float LG  = vec[2 * NS + i], L2G = vec[3 * NS + i], L3G = vec[4 * NS + i];
    const float LH  = vec[5 * NS + i], L2H = vec[6 * NS + i], L3H = vec[7 * NS + i];
    const float c = DTC / 8.0f;
    vw[0 * NS + i] = c * (G + LG + (L2G + L3G) * (1.0f / 3.0f));
    vw[1 * NS + i] = c * (3.0f * G + 2.0f * LG + L2G);
    vw[2 * NS + i] = c * (3.0f * G + LG);
    vw[3 * NS + i] = c * G;
    vw[4 * NS + i] = DTC * (H + 0.5f * LH + L2H * (1.0f / 6.0f) + L3H * (1.0f / 24.0f));
}

__global__ void k_prep1(const float* __restrict__ Lt, const float* __restrict__ G1,
                        float* __restrict__ H, float* __restrict__ base) {
    int idx = blockIdx.x * blockDim.x + threadIdx.x;
    if (idx < NS2) {
        int i = idx >> 9, j = idx & 511;
        float l = Lt[idx], g = G1[idx];
        H[idx]    = l * (1.0f / 6.0f) + g * (1.0f / 24.0f);
        base[idx] = l + 0.5f * g + (i == j ? 1.0f : 0.0f);
    }
}

// ---------------- split-K 512^3 GEMM partials (32x64 tile, K chunk 128) ----------------
__global__ void __launch_bounds__(128) k_gsk(
    const float* __restrict__ A, const float* __restrict__ B, float* __restrict__ part)
{
    __shared__ float As[16][36];
    __shared__ float Bs[16][68];
    const int t  = threadIdx.x;
    const int tx = t & 7, ty = t >> 3;
    const int r0 = blockIdx.y * 32, c0 = blockIdx.x * 64;
    const int kb = blockIdx.z * 128;

    const int ar = t >> 2, ac4 = (t & 3) * 4;
    const int br = t >> 4, bc4 = (t & 15) * 4;

    unsigned long long acc[2][4];
#pragma unroll
    for (int m = 0; m < 2; m++)
#pragma unroll
        for (int p = 0; p < 4; p++) acc[m][p] = 0ull;

    float4 av = *(const float4*)(A + (size_t)(r0 + ar) * NS + kb + ac4);
    float4 b0 = *(const float4*)(B + (size_t)(kb + br) * NS + c0 + bc4);
    float4 b1 = *(const float4*)(B + (size_t)(kb + br + 8) * NS + c0 + bc4);

    for (int it = 0; it < 8; ++it) {
        As[ac4 + 0][ar] = av.x; As[ac4 + 1][ar] = av.y;
        As[ac4 + 2][ar] = av.z; As[ac4 + 3][ar] = av.w;
        *(float4*)&Bs[br][bc4]     = b0;
        *(float4*)&Bs[br + 8][bc4] = b1;
        __syncthreads();
        if (it < 7) {
            const int k0 = kb + (it + 1) * 16;
            av = *(const float4*)(A + (size_t)(r0 + ar) * NS + k0 + ac4);
            b0 = *(const float4*)(B + (size_t)(k0 + br) * NS + c0 + bc4);
            b1 = *(const float4*)(B + (size_t)(k0 + br + 8) * NS + c0 + bc4);
        }
#pragma unroll
        for (int kk = 0; kk < 16; ++kk) {
            float a0 = As[kk][ty * 2 + 0];
            float a1 = As[kk][ty * 2 + 1];
            ulonglong2 bp0 = *(const ulonglong2*)&Bs[kk][tx * 8];
            ulonglong2 bp1 = *(const ulonglong2*)&Bs[kk][tx * 8 + 4];
            unsigned long long bv[4] = {bp0.x, bp0.y, bp1.x, bp1.y};
            unsigned long long av0, av1;
            asm("mov.b64 %0, {%1, %1};" : "=l"(av0) : "f"(a0));
            asm("mov.b64 %0, {%1, %1};" : "=l"(av1) : "f"(a1));
#pragma unroll
            for (int p = 0; p < 4; p++) {
                asm("fma.rn.f32x2 %0, %1, %2, %0;" : "+l"(acc[0][p]) : "l"(av0), "l"(bv[p]));
                asm("fma.rn.f32x2 %0, %1, %2, %0;" : "+l"(acc[1][p]) : "l"(av1), "l"(bv[p]));
            }
        }
        __syncthreads();
    }
    float* po = part + (size_t)blockIdx.z * NS2;
#pragma unroll
    for (int m = 0; m < 2; m++) {
        const int row = r0 + ty * 2 + m;
#pragma unroll
        for (int p = 0; p < 4; p++) {
            float lo, hi;
            asm("mov.b64 {%0, %1}, %2;" : "=f"(lo), "=f"(hi) : "l"(acc[m][p]));
            int col = c0 + tx * 8 + 2 * p;
            po[(size_t)row * NS + col]     = lo;
            po[(size_t)row * NS + col + 1] = hi;
        }
    }
}

// batched split-K over T slots: item = z>>2, ksplit = z&3
__global__ void __launch_bounds__(128) k_gskz(
    float* __restrict__ Tb, float* __restrict__ part,
    int a0, int a1, int a2, int a3, int b0s, int b1s, int b2s, int b3s)
{
    const int item = blockIdx.z >> 2;
    const int ks   = blockIdx.z & 3;
    const int asl  = (item == 0) ? a0 : (item == 1) ? a1 : (item == 2) ? a2 : a3;
    const int bsl  = (item == 0) ? b0s : (item == 1) ? b1s : (item == 2) ? b2s : b3s;
    const float* A = Tb + (size_t)asl * NS2;
    const float* B = Tb + (size_t)bsl * NS2;

    __shared__ float As[16][36];
    __shared__ float Bs[16][68];
    const int t  = threadIdx.x;
    const int tx = t & 7, ty = t >> 3;
    const int r0 = blockIdx.y * 32, c0 = blockIdx.x * 64;
    const int kb = ks * 128;

    const int ar = t >> 2, ac4 = (t & 3) * 4;
    const int br = t >> 4, bc4 = (t & 15) * 4;

    unsigned long long acc[2][4];
#pragma unroll
    for (int m = 0; m < 2; m++)
#pragma unroll
        for (int p = 0; p < 4; p++) acc[m][p] = 0ull;

    float4 av = *(const float4*)(A + (size_t)(r0 + ar) * NS + kb + ac4);
    float4 b0 = *(const float4*)(B + (size_t)(kb + br) * NS + c0 + bc4);
    float4 b1 = *(const float4*)(B + (size_t)(kb + br + 8) * NS + c0 + bc4);

    for (int it = 0; it < 8; ++it) {
        As[ac4 + 0][ar] = av.x; As[ac4 + 1][ar] = av.y;
        As[ac4 + 2][ar] = av.z; As[ac4 + 3][ar] = av.w;
        *(float4*)&Bs[br][bc4]     = b0;
        *(float4*)&Bs[br + 8][bc4] = b1;
        __syncthreads();
        if (it < 7) {
            const int k0 = kb + (it + 1) * 16;
            av = *(const float4*)(A + (size_t)(r0 + ar) * NS + k0 + ac4);
            b0 = *(const float4*)(B + (size_t)(k0 + br) * NS + c0 + bc4);
            b1 = *(const float4*)(B + (size_t)(k0 + br + 8) * NS + c0 + bc4);
        }
#pragma unroll
        for (int kk = 0; kk < 16; ++kk) {
            float a0f = As[kk][ty * 2 + 0];
            float a1f = As[kk][ty * 2 + 1];
            ulonglong2 bp0 = *(const ulonglong2*)&Bs[kk][tx * 8];
            ulonglong2 bp1 = *(const ulonglong2*)&Bs[kk][tx * 8 + 4];
            unsigned long long bv[4] = {bp0.x, bp0.y, bp1.x, bp1.y};
            unsigned long long av0, av1;
            asm("mov.b64 %0, {%1, %1};" : "=l"(av0) : "f"(a0f));
            asm("mov.b64 %0, {%1, %1};" : "=l"(av1) : "f"(a1f));
#pragma unroll
            for (int p = 0; p < 4; p++) {
                asm("fma.rn.f32x2 %0, %1, %2, %0;" : "+l"(acc[0][p]) : "l"(av0), "l"(bv[p]));
                asm("fma.rn.f32x2 %0, %1, %2, %0;" : "+l"(acc[1][p]) : "l"(av1), "l"(bv[p]));
            }
        }
        __syncthreads();
    }
    float* po = part + (size_t)(item * 4 + ks) * NS2;
#pragma unroll
    for (int m = 0; m < 2; m++) {
        const int row = r0 + ty * 2 + m;
#pragma unroll
        for (int p = 0; p < 4; p++) {
            float lo, hi;
            asm("mov.b64 {%0, %1}, %2;" : "=f"(lo), "=f"(hi) : "l"(acc[m][p]));
            int col = c0 + tx * 8 + 2 * p;
            po[(size_t)row * NS + col]     = lo;
            po[(size_t)row * NS + col + 1] = hi;
        }
    }
}

// C = (base?) + sum of 4 K-partials (deterministic fixed order)
__global__ void k_gred(float* __restrict__ C, const float* __restrict__ part,
                       const float* __restrict__ base) {
    int idx = blockIdx.x * 256 + threadIdx.x;
    size_t o = (size_t)idx * 4;
    float4 p0 = *(const float4*)(part + 0 * (size_t)NS2 + o);
    float4 p1 = *(const float4*)(part + 1 * (size_t)NS2 + o);
    float4 p2 = *(const float4*)(part + 2 * (size_t)NS2 + o);
    float4 p3 = *(const float4*)(part + 3 * (size_t)NS2 + o);
    float4 b = base ? *(const float4*)(base + o) : make_float4(0.f, 0.f, 0.f, 0.f);
    float4 r;
    r.x = b.x + (p0.x + p1.x) + (p2.x + p3.x);
    r.y = b.y + (p0.y + p1.y) + (p2.y + p3.y);
    r.z = b.z + (p0.z + p1.z) + (p2.z + p3.z);
    r.w = b.w + (p0.w + p1.w) + (p2.w + p3.w);
    *(float4*)(C + o) = r;
}

__global__ void k_gredz(float* __restrict__ Tb, const float* __restrict__ part,
                        int d0, int d1, int d2, int d3) {
    const int item = blockIdx.y;
    const int dsl  = (item == 0) ? d0 : (item == 1) ? d1 : (item == 2) ? d2 : d3;
    int idx = blockIdx.x * 256 + threadIdx.x;
    size_t o = (size_t)idx * 4;
    const float* p = part + (size_t)(item * 4) * NS2;
    float4 p0 = *(const float4*)(p + 0 * (size_t)NS2 + o);
    float4 p1 = *(const float4*)(p + 1 * (size_t)NS2 + o);
    float4 p2 = *(const float4*)(p + 2 * (size_t)NS2 + o);
    float4 p3 = *(const float4*)(p + 3 * (size_t)NS2 + o);
    float4 r;
    r.x = (p0.x + p1.x) + (p2.x + p3.x);
    r.y = (p0.y + p1.y) + (p2.y + p3.y);
    r.z = (p0.z + p1.z) + (p2.z + p3.z);
    r.w = (p0.w + p1.w) + (p2.w + p3.w);
    *(float4*)(Tb + (size_t)dsl * NS2 + o) = r;
}

// ---------------- vw[j] = [w1..w4,v] @ T_j (j=1..7, batched) ----------------
__global__ void k_vw(const float* __restrict__ Tb, float* __restrict__ vw) {
    const int j = blockIdx.z + 1;
    const float* T = Tb + (size_t)j * NS2;
    const int c = blockIdx.x * 256 + threadIdx.x;

    __shared__ float v0s[5 * NS];
    for (int i = threadIdx.x; i < 5 * NS; i += 256) v0s[i] = vw[i];
    __syncthreads();

    float acc0 = 0.f, acc1 = 0.f, acc2 = 0.f, acc3 = 0.f, acc4 = 0.f;
    for (int k = 0; k < NS; ++k) {
        float tk = T[(size_t)k * NS + c];
        acc0 += v0s[0 * NS + k] * tk;
        acc1 += v0s[1 * NS + k] * tk;
        acc2 += v0s[2 * NS + k] * tk;
        acc3 += v0s[3 * NS + k] * tk;
        acc4 += v0s[4 * NS + k] * tk;
    }
    float* o = vw + (size_t)j * 5 * NS;
    o[0 * NS + c] = acc0; o[1 * NS + c] = acc1; o[2 * NS + c] = acc2;
    o[3 * NS + c] = acc3; o[4 * NS + c] = acc4;
}

__global__ void k_cv(const float* __restrict__ vw, float* __restrict__ cv) {
    int c = blockIdx.x * 256 + threadIdx.x;
    if (c >= NS) return;
    float acc = 0.f;
    for (int j = 0; j < RAD; ++j) {
        acc += vw[((size_t)j * 5 + 4) * NS + c];
        cv[(size_t)j * NS + c] = acc;
    }
}

// ---------------- grouped E0: one block per group of 8 rows ----------------
__device__ __forceinline__ float dev_interp(const float* __restrict__ Tt,
                                            const float* __restrict__ Tv, float tq) {
    if (tq <= Tt[0])      return Tv[0];
    if (tq >= Tt[ND - 1]) return Tv[ND - 1];
    int lo = 0, hi = ND - 1;
    while (hi - lo > 1) {
        int mid = (lo + hi) >> 1;
        if (Tt[mid] <= tq) lo = mid; else hi = mid;
    }
    float x0 = Tt[lo], x1 = Tt[lo + 1];
    return Tv[lo] + (tq - x0) * (Tv[lo + 1] - Tv[lo]) / (x1 - x0);
}

__global__ void k_buildE0(const float* __restrict__ Tt, const float* __restrict__ Tv,
                          const float* __restrict__ iv, const float* __restrict__ vw,
                          const float* __restrict__ cv, float* __restrict__ E0)
{
    const int g = blockIdx.x;       // rows 8g..8g+7
    const int t = threadIdx.x;      // 256
    __shared__ float s[15][4];      // d indices 8g-8 .. 8g+6
    const int d0 = 8 * g - 8;
    if (t < 60) {
        int jj = t >> 2, ii = t & 3;
        int d = d0 + jj;
        if (d >= 0) {
            float tq = (float)d * DTC + (float)ii * 10.0f;
            s[jj][ii] = dev_interp(Tt, Tv, tq);
        }
    }
    __syncthreads();

#pragma unroll 1
    for (int q = 0; q < 8; ++q) {
        const int n = 8 * g + q;
        float* row = E0 + (size_t)n * NS;
        if (n == 0) {
            for (int i = t; i < NS; i += 256) row[i] = iv[i];
            continue;
        }
        const int p = ((n - 1) & 7) + 1;
        const float* cvp = cv + (size_t)(p - 1) * NS;
        for (int i = t; i < NS; i += 256) {
            float acc = cvp[i];
            for (int jj = 0; jj < p; ++jj) {
                const float* sj = s[q + 7 - jj];
                const float* base = vw + (size_t)jj * 5 * NS;
                acc += sj[0] * base[i]          + sj[1] * base[NS + i]
                     + sj[2] * base[2 * NS + i] + sj[3] * base[3 * NS + i];
            }
            row[i] = acc;
        }
    }
}

// ---------------- split-K anchor BK edge (R12 single-buffer body) ----------------
__global__ void __launch_bounds__(128, 4) k_bk_sk(
    const float* __restrict__ V, const float* __restrict__ W,
    float* __restrict__ part, int S, int aoff, int cnt)
{
    __shared__ float As[16][132];
    __shared__ float Bs[16][68];

    const int t  = threadIdx.x;
    const int tx = t & 7;
    const int ty = t >> 3;
    const int r0 = blockIdx.y * 128;
    const int c0 = blockIdx.x * 64;
    const int z  = blockIdx.z;
    const int kb = z * 128;

    const int  ar  = t >> 2;
    const int  ac4 = (t & 3) * 4;
    long gr[4]; bool v[4];
#pragma unroll
    for (int g = 0; g < 4; g++) {
        int lo = r0 + ar + 32 * g;
        v[g]  = lo < cnt;
        gr[g] = (long)lo * S + aoff;
    }

    const int br  = t >> 4;
    const int bc4 = (t & 15) * 4;

    unsigned long long acc[8][4];
#pragma unroll
    for (int m = 0; m < 8; m++)
#pragma unroll
        for (int p = 0; p < 4; p++) acc[m][p] = 0ull;

    const float4 f4z = make_float4(0.f, 0.f, 0.f, 0.f);
    float4 av[4], b0, b1;
#pragma unroll
    for (int g = 0; g < 4; g++)
        av[g] = v[g] ? *(const float4*)(V + gr[g] * NS + kb + ac4) : f4z;
    b0 = *(const float4*)(W + (size_t)(kb + br) * NS + c0 + bc4);
    b1 = *(const float4*)(W + (size_t)(kb + br + 8) * NS + c0 + bc4);

    for (int it = 0; it < 8; ++it) {
#pragma unroll
        for (int g = 0; g < 4; g++) {
            As[ac4 + 0][ar + 32 * g] = av[g].x;
            As[ac4 + 1][ar + 32 * g] = av[g].y;
            As[ac4 + 2][ar + 32 * g] = av[g].z;
            As[ac4 + 3][ar + 32 * g] = av[g].w;
        }
        *(float4*)&Bs[br][bc4]     = b0;
        *(float4*)&Bs[br + 8][bc4] = b1;
        __syncthreads();

        if (it < 7) {
            const int k0 = kb + (it + 1) * 16;
#pragma unroll
            for (int g = 0; g < 4; g++)
                av[g] = v[g] ? *(const float4*)(V + gr[g] * NS + k0 + ac4) : f4z;
            b0 = *(const float4*)(W + (size_t)(k0 + br) * NS + c0 + bc4);
            b1 = *(const float4*)(W + (size_t)(k0 + br + 8) * NS + c0 + bc4);
        }

#pragma unroll
        for (int kk = 0; kk < 16; ++kk) {
            float a[8];
            *(float4*)&a[0] = *(const float4*)&As[kk][ty * 8];
            *(float4*)&a[4] = *(const float4*)&As[kk][ty * 8 + 4];
            ulonglong2 bp0 = *(const ulonglong2*)&Bs[kk][tx * 8];
            ulonglong2 bp1 = *(const ulonglong2*)&Bs[kk][tx * 8 + 4];
            unsigned long long bv[4] = {bp0.x, bp0.y, bp1.x, bp1.y};
#pragma unroll
            for (int m = 0; m < 8; m++) {
                unsigned long long avv;
                asm("mov.b64 %0, {%1, %1};" : "=l"(avv) : "f"(a[m]));
#pragma unroll
                for (int p = 0; p < 4; p++)
                    asm("fma.rn.f32x2 %0, %1, %2, %0;"
                        : "+l"(acc[m][p]) : "l"(avv), "l"(bv[p]));
            }
        }
        __syncthreads();
    }

#pragma unroll
    for (int m = 0; m < 8; m++) {
        const int r = r0 + ty * 8 + m;
        if (r < cnt) {
            float c[8];
#pragma unroll
            for (int p = 0; p < 4; p++)
                asm("mov.b64 {%0, %1}, %2;"
                    : "=f"(c[2 * p]), "=f"(c[2 * p + 1]) : "l"(acc[m][p]));
            float* prow = part + ((size_t)z * SKROWS + r) * NS + c0 + tx * 8;
            *(float4*)prow       = make_float4(c[0], c[1], c[2], c[3]);
            *(float4*)(prow + 4) = make_float4(c[4], c[5], c[6], c[7]);
        }
    }
}

__global__ void k_bk_red(float* __restrict__ V, const float* __restrict__ part,
                         int S, int boff, int cnt)
{
    int idx = blockIdx.x * 256 + threadIdx.x;
    int total = cnt * (NS / 4);
    if (idx >= total) return;
    int r  = idx / (NS / 4);
    int c4 = (idx - r * (NS / 4)) * 4;
    float4 p0 = *(const float4*)(part + ((size_t)0 * SKROWS + r) * NS + c4);
    float4 p1 = *(const float4*)(part + ((size_t)1 * SKROWS + r) * NS + c4);
    float4 p2 = *(const float4*)(part + ((size_t)2 * SKROWS + r) * NS + c4);
    float4 p3 = *(const float4*)(part + ((size_t)3 * SKROWS + r) * NS + c4);
    float* dst = V + ((size_t)r * S + boff) * NS + c4;
    float4 d = *(const float4*)dst;
    d.x += (p0.x + p1.x) + (p2.x + p3.x);
    d.y += (p0.y + p1.y) + (p2.y + p3.y);
    d.z += (p0.z + p1.z) + (p2.z + p3.z);
    d.w += (p0.w + p1.w) + (p2.w + p3.w);
    *(float4*)dst = d;
}

// ---------------- flat fill (R12 single-buffer body): x[8r+q] = E[8r+q] + T_q x[8r] ----------------
__global__ void __launch_bounds__(128, 4) k_fillz(
    float* __restrict__ V, const float* __restrict__ Tb, int cnt)
{
    const int q = blockIdx.z + 1;
    const float* W = Tb + (size_t)q * NS2;

    __shared__ float As[16][132];
    __shared__ float Bs[16][68];

    const int t  = threadIdx.x;
    const int tx = t & 7;
    const int ty = t >> 3;
    const int r0 = blockIdx.y * 128;
    const int c0 = blockIdx.x * 64;

    const int  ar  = t >> 2;
    const int  ac4 = (t & 3) * 4;
    long gr[4]; bool v[4];
#pragma unroll
    for (int g = 0; g < 4; g++) {
        int lo = r0 + ar + 32 * g;
        v[g]  = lo < cnt;
        gr[g] = (long)lo * RAD;
    }

    const int br  = t >> 4;
    const int bc4 = (t & 15) * 4;

    unsigned long long acc[8][4];
#pragma unroll
    for (int m = 0; m < 8; m++)
#pragma unroll
        for (int p = 0; p < 4; p++) acc[m][p] = 0ull;

    const float4 f4z = make_float4(0.f, 0.f, 0.f, 0.f);
    float4 av[4], b0, b1;
#pragma unroll
    for (int g = 0; g < 4; g++)
        av[g] = v[g] ? *(const float4*)(V + gr[g] * NS + ac4) : f4z;
    b0 = *(const float4*)(W + (size_t)br * NS + c0 + bc4);
    b1 = *(const float4*)(W + (size_t)(br + 8) * NS + c0 + bc4);

    for (int it = 0; it < 32; ++it) {
#pragma unroll
        for (int g = 0; g < 4; g++) {
            As[ac4 + 0][ar + 32 * g] = av[g].x;
            As[ac4 + 1][ar + 32 * g] = av[g].y;
            As[ac4 + 2][ar + 32 * g] = av[g].z;
            As[ac4 + 3][ar + 32 * g] = av[g].w;
        }
        *(float4*)&Bs[br][bc4]     = b0;
        *(float4*)&Bs[br + 8][bc4] = b1;
        __syncthreads();

        if (it < 31) {
            const int k0 = (it + 1) * 16;
#pragma unroll
            for (int g = 0; g < 4; g++)
                av[g] = v[g] ? *(const float4*)(V + gr[g] * NS + k0 + ac4) : f4z;
            b0 = *(const float4*)(W + (size_t)(k0 + br) * NS + c0 + bc4);
            b1 = *(const float4*)(W + (size_t)(k0 + br + 8) * NS + c0 + bc4);
        }

#pragma unroll
        for (int kk = 0; kk < 16; ++kk) {
            float a[8];
            *(float4*)&a[0] = *(const float4*)&As[kk][ty * 8];
            *(float4*)&a[4] = *(const float4*)&As[kk][ty * 8 + 4];
            ulonglong2 bp0 = *(const ulonglong2*)&Bs[kk][tx * 8];
            ulonglong2 bp1 = *(const ulonglong2*)&Bs[kk][tx * 8 + 4];
            unsigned long long bv[4] = {bp0.x, bp0.y, bp1.x, bp1.y};
#pragma unroll
            for (int m = 0; m < 8; m++) {
                unsigned long long avv;
                asm("mov.b64 %0, {%1, %1};" : "=l"(avv) : "f"(a[m]));
#pragma unroll
                for (int p = 0; p < 4; p++)
                    asm("fma.rn.f32x2 %0, %1, %2, %0;"
                        : "+l"(acc[m][p]) : "l"(avv), "l"(bv[p]));
            }
        }
        __syncthreads();
    }

#pragma unroll
    for (int m = 0; m < 8; m++) {
        const int r = r0 + ty * 8 + m;
        if (r < cnt) {
            const long dr = (long)r * RAD + q;
            float* erow = V + dr * NS + c0 + tx * 8;
            float4 e0 = *(const float4*)erow;
            float4 e1 = *(const float4*)(erow + 4);
            float c[8];
#pragma unroll
            for (int p = 0; p < 4; p++)
                asm("mov.b64 {%0, %1}, %2;"
                    : "=f"(c[2 * p]), "=f"(c[2 * p + 1]) : "l"(acc[m][p]));
            float4 o0 = make_float4(c[0] + e0.x, c[1] + e0.y, c[2] + e0.z, c[3] + e0.w);
            float4 o1 = make_float4(c[4] + e1.x, c[5] + e1.y, c[6] + e1.z, c[7] + e1.w);
            *(float4*)erow       = o0;
            *(float4*)(erow + 4) = o1;
        }
    }
}

// ---------------- host orchestration (graph-capturable, alloc-free) ----------------
extern "C" void kernel_launch(void* const* d_in, const int* in_sizes, int n_in,
                              void* d_out, int out_size) {
    const float* A  = (const float*)d_in[0];
    const float* Bm = (const float*)d_in[1];
    const float* Q  = (const float*)d_in[2];
    const float* Tt = (const float*)d_in[3];
    const float* Tv = (const float*)d_in[4];
    const float* iv = (const float*)d_in[5];
    float* out = (float*)d_out;

    float *Lt, *G1, *G2, *Tb, *vec, *vw, *cv, *part;
    cudaGetSymbolAddress((void**)&Lt,   d_Lt);
    cudaGetSymbolAddress((void**)&G1,   d_G1);
    cudaGetSymbolAddress((void**)&G2,   d_G2);
    cudaGetSymbolAddress((void**)&Tb,   d_T);
    cudaGetSymbolAddress((void**)&vec,  d_vec);
    cudaGetSymbolAddress((void**)&vw,   d_vw);
    cudaGetSymbolAddress((void**)&cv,   d_cv);
    cudaGetSymbolAddress((void**)&part, d_part);

    // Lt = (dt*A)^T  +  g/h  (fused, one node)
    k_tpose_gh<<<1026, 256>>>(A, Lt, Bm, Q, vec + 0 * NS, vec + 1 * NS);

    // paired L-power chains
    k_matvec2<<<512, 128>>>(A, vec + 0 * NS, vec + 1 * NS, vec + 2 * NS, vec + 5 * NS, DTC);
    k_matvec2<<<512, 128>>>(A, vec + 2 * NS, vec + 5 * NS, vec + 3 * NS, vec + 6 * NS, DTC);
    k_matvec2<<<512, 128>>>(A, vec + 3 * NS, vec + 6 * NS, vec + 4 * NS, vec + 7 * NS, DTC);
    k_combine<<<2, 256>>>(vec, vw);

    const dim3 gsk(8, 16, 4);
    const int RB = NS2 / 4 / 256;  // 256 blocks for full-matrix reduce

    // G1 = Lt^2 ; T1 = (I + Lt + G1/2) + G1 @ (Lt/6 + G1/24)
    k_gsk<<<gsk, 128>>>(Lt, Lt, part);
    k_gred<<<RB, 256>>>(G1, part, nullptr);
    k_prep1<<<1024, 256>>>(Lt, G1, G2, Tb + 0 * (size_t)NS2);
    k_gsk<<<gsk, 128>>>(G1, G2, part);
    k_gred<<<RB, 256>>>(Tb + 1 * (size_t)NS2, part, Tb + 0 * (size_t)NS2);

    // T2 ; {T3,T4} ; {T5..T8} ; T16 ; T32 ; T64 ; T128
    k_gsk<<<gsk, 128>>>(Tb + 1 * (size_t)NS2, Tb + 1 * (size_t)NS2, part);
    k_gred<<<RB, 256>>>(Tb + 2 * (size_t)NS2, part, nullptr);

    k_gskz<<<dim3(8, 16, 8), 128>>>(Tb, part, 1, 2, 0, 0, 2, 2, 0, 0);
    k_gredz<<<dim3(RB, 2), 256>>>(Tb, part, 3, 4, 0, 0);

    k_gskz<<<dim3(8, 16, 16), 128>>>(Tb, part, 1, 2, 3, 4, 4, 4, 4, 4);
    k_gredz<<<dim3(RB, 4), 256>>>(Tb, part, 5, 6, 7, 8);

    for (int s = 8; s <= 11; ++s) {  // T16(9), T32(10), T64(11), T128(12)
        k_gsk<<<gsk, 128>>>(Tb + (size_t)s * NS2, Tb + (size_t)s * NS2, part);
        k_gred<<<RB, 256>>>(Tb + (size_t)(s + 1) * NS2, part, nullptr);
    }

    // vw[j] = [w,v] @ T_j (j=1..7) ; cv cumsums
    k_vw<<<dim3(2, 1, 7), 256>>>(Tb, vw);
    k_cv<<<2, 256>>>(vw, cv);

    // E0 with within-group-of-8 prefixes (grouped blocks)
    k_buildE0<<<NANCH, 256>>>(Tt, Tv, iv, vw, cv, out);

    // ---- anchor Brent-Kung over 2500 anchors (rows = 8*o), levels j=0..4
    for (int j = 0; j < 5; ++j) {            // up-sweep
        const int Sa = 1 << (j + 1);
        const int cnt = NANCH >> (j + 1);
        const int Sm = RAD * Sa;
        const int aoff = RAD * ((1 << j) - 1);
        const int boff = RAD * (Sa - 1);
        dim3 gs(8, (cnt + 127) / 128, 4);
        k_bk_sk<<<gs, 128>>>(out, Tb + (size_t)(8 + j) * NS2, part, Sm, aoff, cnt);
        k_bk_red<<<(cnt * (NS / 4) + 255) / 256, 256>>>(out, part, Sm, boff, cnt);
    }
    for (int j = 4; j >= 0; --j) {           // down-sweep
        const int Sa = 1 << (j + 1);
        const int boffa = Sa - 1 + (1 << j);
        const int cnt = (NANCH - 1 - boffa) / Sa + 1;
        const int Sm = RAD * Sa;
        const int aoff = RAD * (Sa - 1);
        const int boff = RAD * boffa;
        dim3 gs(8, (cnt + 127) / 128, 4);
        k_bk_sk<<<gs, 128>>>(out, Tb + (size_t)(8 + j) * NS2, part, Sm, aoff, cnt);
        k_bk_red<<<(cnt * (NS / 4) + 255) / 256, 256>>>(out, part, Sm, boff, cnt);
    }

    // ---- flat fill: all non-anchor rows in one launch
    dim3 gf(8, (NANCH + 127) / 128, RAD - 1);
    k_fillz<<<gf, 128>>>(out, Tb, NANCH);
    // result in `out`
}